// round 12
// baseline (speedup 1.0000x reference)
#include <cuda_runtime.h>
#include <cuda_fp16.h>
#include <cstdint>
#include <math.h>

// Problem dims (fixed by the dataset)
#define BB 4
#define NN 4096
#define DD 1024
#define HH 16
#define DH 64
#define FF 4096
#define MM (BB * NN)          // 16384
#define TOT ((size_t)MM * DD) // 16,777,216
#define QKVN (3 * DD)         // 3072

// ===================== helpers =====================
__device__ __forceinline__ uint32_t smem_u32(const void* p) {
    uint32_t a;
    asm("{ .reg .u64 t; cvta.to.shared.u64 t, %1; cvt.u32.u64 %0, t; }" : "=r"(a) : "l"(p));
    return a;
}
__device__ __forceinline__ void cp_async16(uint32_t dst, const void* src) {
    asm volatile("cp.async.cg.shared.global [%0], [%1], 16;"
                 :: "r"(dst), "l"(__cvta_generic_to_global(src)));
}
__device__ __forceinline__ void cp_commit() { asm volatile("cp.async.commit_group;" ::: "memory"); }
__device__ __forceinline__ void cp_wait0()  { asm volatile("cp.async.wait_group 0;" ::: "memory"); }
__device__ __forceinline__ void cp_wait1()  { asm volatile("cp.async.wait_group 1;" ::: "memory"); }

#define MMAF16(d, a, b0, b1) \
    asm volatile("mma.sync.aligned.m16n8k16.row.col.f32.f16.f16.f32 " \
        "{%0,%1,%2,%3}, {%4,%5,%6,%7}, {%8,%9}, {%0,%1,%2,%3};" \
        : "+f"((d)[0]), "+f"((d)[1]), "+f"((d)[2]), "+f"((d)[3]) \
        : "r"((a)[0]), "r"((a)[1]), "r"((a)[2]), "r"((a)[3]), "r"(b0), "r"(b1))

#define LDMX4(r, addr) \
    asm volatile("ldmatrix.sync.aligned.m8n8.x4.shared.b16 {%0,%1,%2,%3}, [%4];" \
        : "=r"((r)[0]), "=r"((r)[1]), "=r"((r)[2]), "=r"((r)[3]) : "r"(addr))

// ===================== scratch (static device globals) =====================
__device__ float g_attn[MM * DD];
__device__ float g_Gpart[BB * HH * 8 * DH * DH];
__device__ float g_Wt[BB * HH * DH * DH];
__device__ float g_bqkv[QKVN];
__device__ double g_part[4096][2];
__device__ double g_red[2];

// fp16 operands
__device__ __half g_xf[MM * DD];
__device__ __half g_qkvf[(size_t)MM * QKVN];   // q | k | v interleaved per row
__device__ __half g_apf[MM * DD];              // attnpre (weighted V)
__device__ __half g_wqkvf[3 * DD * DD];
__device__ __half g_wof[DD * DD];
__device__ __half g_w1f[FF * DD];
__device__ __half g_w2f[DD * FF];
__device__ __half g_atf[MM * DD];              // normalized attn (MLP1 input + MLP2 residual)
__device__ __half g_hf[(size_t)MM * FF];
__device__ __half g_out1f[MM * DD];

// ===================== fp32 -> fp16 convert =====================
__global__ void __launch_bounds__(256) cvtf16_kernel(
    const float* __restrict__ src, __half* __restrict__ dst, size_t n4)
{
    const size_t stride = (size_t)gridDim.x * blockDim.x;
    for (size_t i4 = (size_t)blockIdx.x * blockDim.x + threadIdx.x; i4 < n4; i4 += stride) {
        float4 v = ((const float4*)src)[i4];
        ((__half2*)dst)[i4 * 2 + 0] = __floats2half2_rn(v.x, v.y);
        ((__half2*)dst)[i4 * 2 + 1] = __floats2half2_rn(v.z, v.w);
    }
}

// ===================== fp16 single-product HMMA GEMM =====================
// C[m,n] = sum_k A[m,k]*B[n,k] + bias[n] (+res fp32/fp16)(+gelu); fp32 accum.
// Optional fused sum/sumsq reduction of output values into g_part[cta].
#define GW_BM 128
#define GW_BN 128
#define GW_BK 32
#define ROWB 80
#define BUFB (128 * ROWB)
#define F16_STAGEB (2 * BUFB)          // 20480 per stage (A + B)
#define NSTAGE 3
#define F16_SMEM (NSTAGE * F16_STAGEB) // 61440

template <bool HAS_RES, bool RES16, bool GELU, bool OUTF16, bool DO_RED>
__global__ void __launch_bounds__(256, 2) gemm_f16(
    const __half* __restrict__ A, const __half* __restrict__ B,
    const float* __restrict__ bias,
    const float* __restrict__ resf, const __half* __restrict__ resh,
    float* __restrict__ Cf, __half* __restrict__ Ch,
    int M, int N, int K)
{
    extern __shared__ char sm[];
    const int tid = threadIdx.x;
    const int wid = tid >> 5;
    const int lane = tid & 31;
    const int wm = wid & 3;
    const int wn = wid >> 2;
    const int bm = blockIdx.y * GW_BM;
    const int bn = blockIdx.x * GW_BN;
    const int KT = K / GW_BK;
    const uint32_t smb = smem_u32(sm);

    auto load_stage = [&](int kt) {
        const uint32_t sb = smb + (uint32_t)(kt % NSTAGE) * F16_STAGEB;
        const int k0 = kt * GW_BK;
#pragma unroll
        for (int i = 0; i < 4; i++) {
            const int c = tid + i * 256;
            const int buf = c >> 9;
            const int cc = c & 511;
            const int row = cc >> 2;
            const int qq = cc & 3;
            const __half* gb = buf ? B : A;
            const int grow = (buf ? bn : bm) + row;
            const void* src = gb + (size_t)grow * K + k0 + qq * 8;
            cp_async16(sb + buf * BUFB + row * ROWB + qq * 16, src);
        }
    };

    float acc[2][8][4];
#pragma unroll
    for (int mt = 0; mt < 2; mt++)
#pragma unroll
        for (int nt = 0; nt < 8; nt++)
#pragma unroll
            for (int r = 0; r < 4; r++) acc[mt][nt][r] = 0.0f;

    load_stage(0);
    cp_commit();
    if (KT > 1) { load_stage(1); cp_commit(); }

    const int lr = lane & 7;
    const int a_row = wm * 32 + lr + ((lane & 8) ? 8 : 0);
    const int a_kb  = (lane & 16) ? 16 : 0;
    const int b_row = wn * 64 + lr + ((lane & 16) ? 8 : 0);
    const int b_kb  = (lane & 8) ? 16 : 0;

    for (int kt = 0; kt < KT; kt++) {
        if (kt + 1 < KT) cp_wait1(); else cp_wait0();
        __syncthreads();

        if (kt + 2 < KT) {
            load_stage(kt + 2);
            cp_commit();
        }

        const uint32_t sb = smb + (uint32_t)(kt % NSTAGE) * F16_STAGEB;
        const uint32_t As = sb;
        const uint32_t Bs = sb + BUFB;

#pragma unroll
        for (int k16 = 0; k16 < 2; k16++) {
            const int kc = k16 * 32;
            uint32_t af[2][4];
#pragma unroll
            for (int mt = 0; mt < 2; mt++)
                LDMX4(af[mt], As + (uint32_t)((a_row + mt * 16) * ROWB + kc + a_kb));
#pragma unroll
            for (int p = 0; p < 4; p++) {
                uint32_t bf[4];
                LDMX4(bf, Bs + (uint32_t)((b_row + p * 16) * ROWB + kc + b_kb));
#pragma unroll
                for (int sub = 0; sub < 2; sub++) {
                    const int nt = p * 2 + sub;
#pragma unroll
                    for (int mt = 0; mt < 2; mt++)
                        MMAF16(acc[mt][nt], af[mt], bf[sub * 2], bf[sub * 2 + 1]);
                }
            }
        }
        __syncthreads();
    }

    float rs = 0.0f, rs2 = 0.0f;

#pragma unroll
    for (int mt = 0; mt < 2; mt++) {
        const int r0 = bm + wm * 32 + mt * 16 + (lane >> 2);
#pragma unroll
        for (int nt = 0; nt < 8; nt++) {
            const int c = bn + wn * 64 + nt * 8 + ((lane & 3) << 1);
            const float b0 = bias[c], b1 = bias[c + 1];
#pragma unroll
            for (int half = 0; half < 2; half++) {
                const int row = r0 + half * 8;
                float v0 = acc[mt][nt][half * 2 + 0] + b0;
                float v1 = acc[mt][nt][half * 2 + 1] + b1;
                if (HAS_RES) {
                    if (RES16) {
                        const __half2 rr = *(const __half2*)(resh + (size_t)row * N + c);
                        const float2 rf = __half22float2(rr);
                        v0 += rf.x; v1 += rf.y;
                    } else {
                        const float2 rr = *(const float2*)(resf + (size_t)row * N + c);
                        v0 += rr.x; v1 += rr.y;
                    }
                }
                if (GELU) {
                    v0 = 0.5f * v0 * (1.0f + erff(v0 * 0.70710678118654752f));
                    v1 = 0.5f * v1 * (1.0f + erff(v1 * 0.70710678118654752f));
                }
                if (DO_RED) {
                    rs += v0 + v1;
                    rs2 += v0 * v0 + v1 * v1;
                }
                if (OUTF16) {
                    *(__half2*)(Ch + (size_t)row * N + c) = __floats2half2_rn(v0, v1);
                } else {
                    float2 o; o.x = v0; o.y = v1;
                    *(float2*)(Cf + (size_t)row * N + c) = o;
                }
            }
        }
    }

    if (DO_RED) {
#pragma unroll
        for (int o = 16; o > 0; o >>= 1) {
            rs += __shfl_down_sync(0xFFFFFFFFu, rs, o);
            rs2 += __shfl_down_sync(0xFFFFFFFFu, rs2, o);
        }
        __shared__ float shr[2][8];
        if (lane == 0) { shr[0][wid] = rs; shr[1][wid] = rs2; }
        __syncthreads();
        if (tid == 0) {
            double a = 0.0, b = 0.0;
#pragma unroll
            for (int i = 0; i < 8; i++) { a += (double)shr[0][i]; b += (double)shr[1][i]; }
            const int cid = blockIdx.y * gridDim.x + blockIdx.x;
            g_part[cid][0] = a;
            g_part[cid][1] = b;
        }
    }
}

// ===================== attention small ops =====================
// Gram from fp16 qkv buffer (q at col 0, k at col 1024, row stride QKVN)
__global__ void __launch_bounds__(256) gram_kernel(
    const __half* __restrict__ qkv, float* __restrict__ Gpart)
{
    const int bh = blockIdx.x;
    const int ns = blockIdx.y;
    const int b = bh >> 4, h = bh & 15;
    const int tid = threadIdx.x;
    __shared__ float Qs[32][68];
    __shared__ float Ks[32][68];

    float acc[4][4];
#pragma unroll
    for (int i = 0; i < 4; i++)
#pragma unroll
        for (int j = 0; j < 4; j++) acc[i][j] = 0.0f;

    const int ty = tid >> 4, tx = tid & 15;
    const size_t base = ((size_t)b * NN) * QKVN + h * DH;
    const int n0s = ns * 512;

    const int lrow = tid >> 3;      // 0..31
    const int lch  = tid & 7;       // 0..7 (8 halves each)

    for (int n0 = n0s; n0 < n0s + 512; n0 += 32) {
        const size_t roff = base + (size_t)(n0 + lrow) * QKVN + lch * 8;
        const uint4 qv = *(const uint4*)(qkv + roff);
        const uint4 kv = *(const uint4*)(qkv + roff + 1024);
        {
            float2 f0 = __half22float2(*(const __half2*)&qv.x);
            float2 f1 = __half22float2(*(const __half2*)&qv.y);
            float2 f2 = __half22float2(*(const __half2*)&qv.z);
            float2 f3 = __half22float2(*(const __half2*)&qv.w);
            float4 a; a.x = f0.x; a.y = f0.y; a.z = f1.x; a.w = f1.y;
            float4 c; c.x = f2.x; c.y = f2.y; c.z = f3.x; c.w = f3.y;
            *(float4*)&Qs[lrow][lch * 8] = a;
            *(float4*)&Qs[lrow][lch * 8 + 4] = c;
        }
        {
            float2 f0 = __half22float2(*(const __half2*)&kv.x);
            float2 f1 = __half22float2(*(const __half2*)&kv.y);
            float2 f2 = __half22float2(*(const __half2*)&kv.z);
            float2 f3 = __half22float2(*(const __half2*)&kv.w);
            float4 a; a.x = f0.x; a.y = f0.y; a.z = f1.x; a.w = f1.y;
            float4 c; c.x = f2.x; c.y = f2.y; c.z = f3.x; c.w = f3.y;
            *(float4*)&Ks[lrow][lch * 8] = a;
            *(float4*)&Ks[lrow][lch * 8 + 4] = c;
        }
        __syncthreads();
#pragma unroll
        for (int kk = 0; kk < 32; kk++) {
            float qr[4], kr[4];
#pragma unroll
            for (int i = 0; i < 4; i++) qr[i] = Qs[kk][ty * 4 + i];
#pragma unroll
            for (int j = 0; j < 4; j++) kr[j] = Ks[kk][tx * 4 + j];
#pragma unroll
            for (int i = 0; i < 4; i++)
#pragma unroll
                for (int j = 0; j < 4; j++) acc[i][j] += qr[i] * kr[j];
        }
        __syncthreads();
    }

    float* Gout = Gpart + ((size_t)bh * 8 + ns) * (DH * DH);
#pragma unroll
    for (int i = 0; i < 4; i++)
#pragma unroll
        for (int j = 0; j < 4; j++)
            Gout[(ty * 4 + i) * DH + tx * 4 + j] = acc[i][j];
}

__global__ void __launch_bounds__(256) weights_kernel(
    const float* __restrict__ Gpart, float* __restrict__ Wt)
{
    const int bh = blockIdx.x;
    const int tid = threadIdx.x;
    __shared__ float Gs[DH][DH];
    __shared__ float ct[DH], st[DH];

    for (int e = tid; e < DH * DH; e += 256) {
        float sacc = 0.0f;
#pragma unroll
        for (int p = 0; p < 8; p++)
            sacc += Gpart[((size_t)bh * 8 + p) * (DH * DH) + e];
        Gs[e >> 6][e & 63] = sacc;
    }
    if (tid < DH) {
        float a = 6.283185307179586f * (float)tid / 64.0f;
        ct[tid] = cosf(a);
        st[tid] = sinf(a);
    }
    __syncthreads();

    const int i = tid >> 2;
    const int j0 = (tid & 3) * 16;
    for (int jj = 0; jj < 16; jj++) {
        const int j = j0 + jj;
        float re = 0.0f, im = 0.0f;
#pragma unroll
        for (int kk = 0; kk < DH; kk++) {
            const int t = (kk * j) & 63;
            const float g = Gs[i][kk];
            re += g * ct[t];
            im += g * st[t];
        }
        Wt[(size_t)bh * (DH * DH) + i * DH + j] = sqrtf(re * re + im * im);
    }
}

// attnpre = weights @ v per (b,h); v from qkv buffer at col offset 2048; fp16 out
__global__ void __launch_bounds__(256) applyw_kernel(
    const __half* __restrict__ qkv, const float* __restrict__ Wt,
    __half* __restrict__ ohf)
{
    const int bh = blockIdx.x;
    const int b = bh >> 4, h = bh & 15;
    const int tid = threadIdx.x;
    __shared__ float Ws[DH][DH + 1];
    __shared__ float Vs[4][DH];

    for (int e = tid; e < DH * DH; e += 256)
        Ws[e >> 6][e & 63] = Wt[(size_t)bh * (DH * DH) + e];
    __syncthreads();

    const int nn = tid >> 6;
    const int i = tid & 63;
    const size_t vbase = ((size_t)b * NN) * QKVN + 2048 + h * DH;
    const size_t obase = ((size_t)b * NN) * DD + h * DH;
    const int n0 = blockIdx.y * 64;

    for (int n = n0; n < n0 + 64; n += 4) {
        Vs[nn][i] = __half2float(qkv[vbase + (size_t)(n + nn) * QKVN + i]);
        __syncthreads();
        float acc = 0.0f;
#pragma unroll
        for (int j = 0; j < DH; j++) acc += Ws[i][j] * Vs[nn][j];
        ohf[obase + (size_t)(n + nn) * DD + i] = __float2half(acc);
        __syncthreads();
    }
}

// ===================== reduction finalize + norms =====================
__global__ void __launch_bounds__(256) red2_kernel(int nb)
{
    double a = 0.0, b = 0.0;
    for (int i = threadIdx.x; i < nb; i += 256) { a += g_part[i][0]; b += g_part[i][1]; }
    __shared__ double sa[256], sb[256];
    sa[threadIdx.x] = a;
    sb[threadIdx.x] = b;
    __syncthreads();
    for (int o = 128; o > 0; o >>= 1) {
        if (threadIdx.x < o) { sa[threadIdx.x] += sa[threadIdx.x + o]; sb[threadIdx.x] += sb[threadIdx.x + o]; }
        __syncthreads();
    }
    if (threadIdx.x == 0) { g_red[0] = sa[0]; g_red[1] = sb[0]; }
}

// norm1: fp32 input -> fp16 output only
__global__ void __launch_bounds__(256) norm_f32f16_kernel(
    const float* __restrict__ x, const float* __restrict__ alpha,
    const float* __restrict__ beta, const float* __restrict__ eps,
    __half* __restrict__ yh, size_t n)
{
    const double Md = (double)n;
    const double mean = g_red[0] / Md;
    const double var = (g_red[1] - Md * mean * mean) / (Md - 1.0);
    const float sd = (float)sqrt(var);

    const size_t n4 = n >> 2;
    const size_t stride = (size_t)gridDim.x * blockDim.x;
    for (size_t i4 = (size_t)blockIdx.x * blockDim.x + threadIdx.x; i4 < n4; i4 += stride) {
        float4 v = ((const float4*)x)[i4];
        const int d = (int)((i4 * 4) & (DD - 1));
        v.x = v.x / (sd + eps[d + 0]) * alpha[d + 0] + beta[d + 0];
        v.y = v.y / (sd + eps[d + 1]) * alpha[d + 1] + beta[d + 1];
        v.z = v.z / (sd + eps[d + 2]) * alpha[d + 2] + beta[d + 2];
        v.w = v.w / (sd + eps[d + 3]) * alpha[d + 3] + beta[d + 3];
        ((__half2*)yh)[i4 * 2 + 0] = __floats2half2_rn(v.x, v.y);
        ((__half2*)yh)[i4 * 2 + 1] = __floats2half2_rn(v.z, v.w);
    }
}

// norm2: fp16 input -> fp32 output (final)
__global__ void __launch_bounds__(256) norm_f16f32_kernel(
    const __half* __restrict__ x, const float* __restrict__ alpha,
    const float* __restrict__ beta, const float* __restrict__ eps,
    float* __restrict__ y, size_t n)
{
    const double Md = (double)n;
    const double mean = g_red[0] / Md;
    const double var = (g_red[1] - Md * mean * mean) / (Md - 1.0);
    const float sd = (float)sqrt(var);

    const size_t n4 = n >> 2;
    const size_t stride = (size_t)gridDim.x * blockDim.x;
    for (size_t i4 = (size_t)blockIdx.x * blockDim.x + threadIdx.x; i4 < n4; i4 += stride) {
        const uint2 raw = ((const uint2*)x)[i4];
        const float2 f0 = __half22float2(*(const __half2*)&raw.x);
        const float2 f1 = __half22float2(*(const __half2*)&raw.y);
        float4 v; v.x = f0.x; v.y = f0.y; v.z = f1.x; v.w = f1.y;
        const int d = (int)((i4 * 4) & (DD - 1));
        v.x = v.x / (sd + eps[d + 0]) * alpha[d + 0] + beta[d + 0];
        v.y = v.y / (sd + eps[d + 1]) * alpha[d + 1] + beta[d + 1];
        v.z = v.z / (sd + eps[d + 2]) * alpha[d + 2] + beta[d + 2];
        v.w = v.w / (sd + eps[d + 3]) * alpha[d + 3] + beta[d + 3];
        ((float4*)y)[i4] = v;
    }
}

// ===================== launch =====================
extern "C" void kernel_launch(void* const* d_in, const int* in_sizes, int n_in,
                              void* d_out, int out_size)
{
    const float* x    = (const float*)d_in[0];
    const float* wq_w = (const float*)d_in[1];
    const float* wq_b = (const float*)d_in[2];
    const float* wk_w = (const float*)d_in[3];
    const float* wk_b = (const float*)d_in[4];
    const float* wv_w = (const float*)d_in[5];
    const float* wv_b = (const float*)d_in[6];
    const float* wo_w = (const float*)d_in[7];
    const float* wo_b = (const float*)d_in[8];
    const float* w1   = (const float*)d_in[9];
    const float* b1   = (const float*)d_in[10];
    const float* w2   = (const float*)d_in[11];
    const float* b2   = (const float*)d_in[12];
    const float* an_a = (const float*)d_in[13];
    const float* an_b = (const float*)d_in[14];
    const float* an_e = (const float*)d_in[15];
    const float* mn_a = (const float*)d_in[16];
    const float* mn_b = (const float*)d_in[17];
    const float* mn_e = (const float*)d_in[18];
    float* out = (float*)d_out;

    float *attn, *Gpart, *Wt, *bqkv;
    cudaGetSymbolAddress((void**)&attn, g_attn);
    cudaGetSymbolAddress((void**)&Gpart, g_Gpart);
    cudaGetSymbolAddress((void**)&Wt, g_Wt);
    cudaGetSymbolAddress((void**)&bqkv, g_bqkv);

    __half *xf, *qkvf, *apf, *wqkvf, *wof, *w1f, *w2f, *atf, *hf, *out1f;
    cudaGetSymbolAddress((void**)&xf, g_xf);
    cudaGetSymbolAddress((void**)&qkvf, g_qkvf);
    cudaGetSymbolAddress((void**)&apf, g_apf);
    cudaGetSymbolAddress((void**)&wqkvf, g_wqkvf);
    cudaGetSymbolAddress((void**)&wof, g_wof);
    cudaGetSymbolAddress((void**)&w1f, g_w1f);
    cudaGetSymbolAddress((void**)&w2f, g_w2f);
    cudaGetSymbolAddress((void**)&atf, g_atf);
    cudaGetSymbolAddress((void**)&hf, g_hf);
    cudaGetSymbolAddress((void**)&out1f, g_out1f);

    cudaFuncSetAttribute(gemm_f16<false, false, false, true,  false>, cudaFuncAttributeMaxDynamicSharedMemorySize, F16_SMEM);
    cudaFuncSetAttribute(gemm_f16<true,  false, false, false, true >, cudaFuncAttributeMaxDynamicSharedMemorySize, F16_SMEM);
    cudaFuncSetAttribute(gemm_f16<false, false, true,  true,  false>, cudaFuncAttributeMaxDynamicSharedMemorySize, F16_SMEM);
    cudaFuncSetAttribute(gemm_f16<true,  true,  false, true,  true >, cudaFuncAttributeMaxDynamicSharedMemorySize, F16_SMEM);

    // ---- conversions + bias concat ----
    cvtf16_kernel<<<1024, 256>>>(x, xf, TOT / 4);
    cvtf16_kernel<<<512, 256>>>(wq_w, wqkvf + 0 * DD * DD, (size_t)DD * DD / 4);
    cvtf16_kernel<<<512, 256>>>(wk_w, wqkvf + 1 * DD * DD, (size_t)DD * DD / 4);
    cvtf16_kernel<<<512, 256>>>(wv_w, wqkvf + 2 * DD * DD, (size_t)DD * DD / 4);
    cvtf16_kernel<<<512, 256>>>(wo_w, wof, (size_t)DD * DD / 4);
    cvtf16_kernel<<<1024, 256>>>(w1, w1f, (size_t)FF * DD / 4);
    cvtf16_kernel<<<1024, 256>>>(w2, w2f, (size_t)DD * FF / 4);
    cudaMemcpyAsync(bqkv + 0 * DD, wq_b, DD * sizeof(float), cudaMemcpyDeviceToDevice);
    cudaMemcpyAsync(bqkv + 1 * DD, wk_b, DD * sizeof(float), cudaMemcpyDeviceToDevice);
    cudaMemcpyAsync(bqkv + 2 * DD, wv_b, DD * sizeof(float), cudaMemcpyDeviceToDevice);

    const dim3 gQKV(QKVN / GW_BN, MM / GW_BM);  // (24, 128)
    const dim3 gProj(DD / GW_BN, MM / GW_BM);   // (8, 128)
    const dim3 gMlp1(FF / GW_BN, MM / GW_BM);   // (32, 128)

    // ---- fused Q|K|V projection (fp16 out) ----
    gemm_f16<false, false, false, true, false><<<gQKV, 256, F16_SMEM>>>(
        xf, wqkvf, bqkv, nullptr, nullptr, nullptr, qkvf, MM, QKVN, DD);

    // ---- FFT attention (collapsed form) ----
    gram_kernel<<<dim3(BB * HH, 8), 256>>>(qkvf, Gpart);
    weights_kernel<<<BB * HH, 256>>>(Gpart, Wt);
    applyw_kernel<<<dim3(BB * HH, NN / 64), 256>>>(qkvf, Wt, apf);

    // ---- output projection + residual (fp32 out), fused sum/sumsq ----
    gemm_f16<true, false, false, false, true><<<gProj, 256, F16_SMEM>>>(
        apf, wof, wo_b, x, nullptr, attn, nullptr, MM, DD, DD);

    // ---- rmsnorm 1 -> fp16 (MLP1 input + MLP2 residual) ----
    red2_kernel<<<1, 256>>>(1024);
    norm_f32f16_kernel<<<2048, 256>>>(attn, an_a, an_b, an_e, atf, TOT);

    // ---- MLP (fp16) ----
    gemm_f16<false, false, true, true, false><<<gMlp1, 256, F16_SMEM>>>(
        atf, w1f, b1, nullptr, nullptr, nullptr, hf, MM, FF, DD);
    gemm_f16<true, true, false, true, true><<<gProj, 256, F16_SMEM>>>(
        hf, w2f, b2, nullptr, atf, nullptr, out1f, MM, DD, FF);

    // ---- rmsnorm 2 -> final fp32 output ----
    red2_kernel<<<1, 256>>>(1024);
    norm_f16f32_kernel<<<2048, 256>>>(out1f, mn_a, mn_b, mn_e, out, TOT);
}

// round 13
// speedup vs baseline: 1.0119x; 1.0119x over previous
#include <cuda_runtime.h>
#include <cuda_fp16.h>
#include <cstdint>
#include <math.h>

// Problem dims (fixed by the dataset)
#define BB 4
#define NN 4096
#define DD 1024
#define HH 16
#define DH 64
#define FF 4096
#define MM (BB * NN)          // 16384
#define TOT ((size_t)MM * DD) // 16,777,216

// ===================== helpers =====================
__device__ __forceinline__ uint32_t smem_u32(const void* p) {
    uint32_t a;
    asm("{ .reg .u64 t; cvta.to.shared.u64 t, %1; cvt.u32.u64 %0, t; }" : "=r"(a) : "l"(p));
    return a;
}
__device__ __forceinline__ void cp_async16(uint32_t dst, const void* src) {
    asm volatile("cp.async.cg.shared.global [%0], [%1], 16;"
                 :: "r"(dst), "l"(__cvta_generic_to_global(src)));
}
__device__ __forceinline__ void cp_commit() { asm volatile("cp.async.commit_group;" ::: "memory"); }
__device__ __forceinline__ void cp_wait0()  { asm volatile("cp.async.wait_group 0;" ::: "memory"); }
__device__ __forceinline__ void cp_wait1()  { asm volatile("cp.async.wait_group 1;" ::: "memory"); }

#define MMAF16(d, a, b0, b1) \
    asm volatile("mma.sync.aligned.m16n8k16.row.col.f32.f16.f16.f32 " \
        "{%0,%1,%2,%3}, {%4,%5,%6,%7}, {%8,%9}, {%0,%1,%2,%3};" \
        : "+f"((d)[0]), "+f"((d)[1]), "+f"((d)[2]), "+f"((d)[3]) \
        : "r"((a)[0]), "r"((a)[1]), "r"((a)[2]), "r"((a)[3]), "r"(b0), "r"(b1))

#define LDMX4(r, addr) \
    asm volatile("ldmatrix.sync.aligned.m8n8.x4.shared.b16 {%0,%1,%2,%3}, [%4];" \
        : "=r"((r)[0]), "=r"((r)[1]), "=r"((r)[2]), "=r"((r)[3]) : "r"(addr))

// ===================== scratch (static device globals) =====================
__device__ float g_attn[MM * DD];
__device__ float g_out1[MM * DD];
__device__ float g_Gpart[BB * HH * 8 * DH * DH];
__device__ float g_Wt[BB * HH * DH * DH];
__device__ double g_part[4096][2];
__device__ double g_red[2];

// fp16 operands
__device__ __half g_xf[MM * DD];
__device__ __half g_qf[MM * DD];
__device__ __half g_kf[MM * DD];
__device__ __half g_vf[MM * DD];
__device__ __half g_apf[MM * DD];          // attnpre (weighted V)
__device__ __half g_wqf[DD * DD];
__device__ __half g_wkf[DD * DD];
__device__ __half g_wvf[DD * DD];
__device__ __half g_wof[DD * DD];
__device__ __half g_w1f[FF * DD];
__device__ __half g_w2f[DD * FF];
__device__ __half g_atf[MM * DD];
__device__ __half g_hf[(size_t)MM * FF];

// ===================== merged fp32 -> fp16 convert (x + all weights) ==========
__global__ void __launch_bounds__(256) cvt_all_kernel(
    const float* __restrict__ x,  const float* __restrict__ wq,
    const float* __restrict__ wk, const float* __restrict__ wv,
    const float* __restrict__ wo, const float* __restrict__ w1,
    const float* __restrict__ w2,
    __half* __restrict__ xf,  __half* __restrict__ wqf,
    __half* __restrict__ wkf, __half* __restrict__ wvf,
    __half* __restrict__ wof, __half* __restrict__ w1f,
    __half* __restrict__ w2f)
{
    const size_t SX = TOT / 4;                 // 4,194,304
    const size_t SW = (size_t)DD * DD / 4;     // 262,144
    const size_t SF = (size_t)FF * DD / 4;     // 1,048,576
    const size_t e0 = SX;
    const size_t e1 = e0 + SW;
    const size_t e2 = e1 + SW;
    const size_t e3 = e2 + SW;
    const size_t e4 = e3 + SW;
    const size_t e5 = e4 + SF;
    const size_t e6 = e5 + SF;
    const size_t stride = (size_t)gridDim.x * blockDim.x;
    for (size_t i = (size_t)blockIdx.x * blockDim.x + threadIdx.x; i < e6; i += stride) {
        const float* s; __half* d; size_t off;
        if (i < e0)      { s = x;  d = xf;  off = i; }
        else if (i < e1) { s = wq; d = wqf; off = i - e0; }
        else if (i < e2) { s = wk; d = wkf; off = i - e1; }
        else if (i < e3) { s = wv; d = wvf; off = i - e2; }
        else if (i < e4) { s = wo; d = wof; off = i - e3; }
        else if (i < e5) { s = w1; d = w1f; off = i - e4; }
        else             { s = w2; d = w2f; off = i - e5; }
        float4 v = ((const float4*)s)[off];
        ((__half2*)d)[off * 2 + 0] = __floats2half2_rn(v.x, v.y);
        ((__half2*)d)[off * 2 + 1] = __floats2half2_rn(v.z, v.w);
    }
}

// ===================== fp16 single-product HMMA GEMM (R11-verified) ==========
#define GW_BM 128
#define GW_BN 128
#define GW_BK 32
#define ROWB 80
#define BUFB (128 * ROWB)
#define F16_STAGEB (2 * BUFB)          // 20480 per stage (A + B)
#define NSTAGE 3
#define F16_SMEM (NSTAGE * F16_STAGEB) // 61440

template <bool HAS_RES, bool GELU, bool OUTF16, bool DO_RED>
__global__ void __launch_bounds__(256, 2) gemm_f16(
    const __half* __restrict__ A, const __half* __restrict__ B,
    const float* __restrict__ bias, const float* __restrict__ res,
    float* __restrict__ Cf, __half* __restrict__ Ch,
    int M, int N, int K)
{
    extern __shared__ char sm[];
    const int tid = threadIdx.x;
    const int wid = tid >> 5;
    const int lane = tid & 31;
    const int wm = wid & 3;
    const int wn = wid >> 2;
    const int bm = blockIdx.y * GW_BM;
    const int bn = blockIdx.x * GW_BN;
    const int KT = K / GW_BK;
    const uint32_t smb = smem_u32(sm);

    auto load_stage = [&](int kt) {
        const uint32_t sb = smb + (uint32_t)(kt % NSTAGE) * F16_STAGEB;
        const int k0 = kt * GW_BK;
#pragma unroll
        for (int i = 0; i < 4; i++) {
            const int c = tid + i * 256;
            const int buf = c >> 9;
            const int cc = c & 511;
            const int row = cc >> 2;
            const int qq = cc & 3;
            const __half* gb = buf ? B : A;
            const int grow = (buf ? bn : bm) + row;
            const void* src = gb + (size_t)grow * K + k0 + qq * 8;
            cp_async16(sb + buf * BUFB + row * ROWB + qq * 16, src);
        }
    };

    float acc[2][8][4];
#pragma unroll
    for (int mt = 0; mt < 2; mt++)
#pragma unroll
        for (int nt = 0; nt < 8; nt++)
#pragma unroll
            for (int r = 0; r < 4; r++) acc[mt][nt][r] = 0.0f;

    load_stage(0);
    cp_commit();
    if (KT > 1) { load_stage(1); cp_commit(); }

    const int lr = lane & 7;
    const int a_row = wm * 32 + lr + ((lane & 8) ? 8 : 0);
    const int a_kb  = (lane & 16) ? 16 : 0;
    const int b_row = wn * 64 + lr + ((lane & 16) ? 8 : 0);
    const int b_kb  = (lane & 8) ? 16 : 0;

    for (int kt = 0; kt < KT; kt++) {
        if (kt + 1 < KT) cp_wait1(); else cp_wait0();
        __syncthreads();

        if (kt + 2 < KT) {
            load_stage(kt + 2);
            cp_commit();
        }

        const uint32_t sb = smb + (uint32_t)(kt % NSTAGE) * F16_STAGEB;
        const uint32_t As = sb;
        const uint32_t Bs = sb + BUFB;

#pragma unroll
        for (int k16 = 0; k16 < 2; k16++) {
            const int kc = k16 * 32;
            uint32_t af[2][4];
#pragma unroll
            for (int mt = 0; mt < 2; mt++)
                LDMX4(af[mt], As + (uint32_t)((a_row + mt * 16) * ROWB + kc + a_kb));
#pragma unroll
            for (int p = 0; p < 4; p++) {
                uint32_t bf[4];
                LDMX4(bf, Bs + (uint32_t)((b_row + p * 16) * ROWB + kc + b_kb));
#pragma unroll
                for (int sub = 0; sub < 2; sub++) {
                    const int nt = p * 2 + sub;
#pragma unroll
                    for (int mt = 0; mt < 2; mt++)
                        MMAF16(acc[mt][nt], af[mt], bf[sub * 2], bf[sub * 2 + 1]);
                }
            }
        }
        __syncthreads();
    }

    float rs = 0.0f, rs2 = 0.0f;

#pragma unroll
    for (int mt = 0; mt < 2; mt++) {
        const int r0 = bm + wm * 32 + mt * 16 + (lane >> 2);
#pragma unroll
        for (int nt = 0; nt < 8; nt++) {
            const int c = bn + wn * 64 + nt * 8 + ((lane & 3) << 1);
            const float b0 = bias[c], b1 = bias[c + 1];
#pragma unroll
            for (int half = 0; half < 2; half++) {
                const int row = r0 + half * 8;
                float v0 = acc[mt][nt][half * 2 + 0] + b0;
                float v1 = acc[mt][nt][half * 2 + 1] + b1;
                if (HAS_RES) {
                    const float2 rr = *(const float2*)(res + (size_t)row * N + c);
                    v0 += rr.x; v1 += rr.y;
                }
                if (GELU) {
                    v0 = 0.5f * v0 * (1.0f + erff(v0 * 0.70710678118654752f));
                    v1 = 0.5f * v1 * (1.0f + erff(v1 * 0.70710678118654752f));
                }
                if (DO_RED) {
                    rs += v0 + v1;
                    rs2 += v0 * v0 + v1 * v1;
                }
                if (OUTF16) {
                    *(__half2*)(Ch + (size_t)row * N + c) = __floats2half2_rn(v0, v1);
                } else {
                    float2 o; o.x = v0; o.y = v1;
                    *(float2*)(Cf + (size_t)row * N + c) = o;
                }
            }
        }
    }

    if (DO_RED) {
#pragma unroll
        for (int o = 16; o > 0; o >>= 1) {
            rs += __shfl_down_sync(0xFFFFFFFFu, rs, o);
            rs2 += __shfl_down_sync(0xFFFFFFFFu, rs2, o);
        }
        __shared__ float shr[2][8];
        if (lane == 0) { shr[0][wid] = rs; shr[1][wid] = rs2; }
        __syncthreads();
        if (tid == 0) {
            double a = 0.0, b = 0.0;
#pragma unroll
            for (int i = 0; i < 8; i++) { a += (double)shr[0][i]; b += (double)shr[1][i]; }
            const int cid = blockIdx.y * gridDim.x + blockIdx.x;
            g_part[cid][0] = a;
            g_part[cid][1] = b;
        }
    }
}

// ===================== attention small ops =====================
// Gram from fp16 q/k (contiguous, row stride DD)
__global__ void __launch_bounds__(256) gram_kernel(
    const __half* __restrict__ qf, const __half* __restrict__ kf,
    float* __restrict__ Gpart)
{
    const int bh = blockIdx.x;
    const int ns = blockIdx.y;
    const int b = bh >> 4, h = bh & 15;
    const int tid = threadIdx.x;
    __shared__ float Qs[32][68];
    __shared__ float Ks[32][68];

    float acc[4][4];
#pragma unroll
    for (int i = 0; i < 4; i++)
#pragma unroll
        for (int j = 0; j < 4; j++) acc[i][j] = 0.0f;

    const int ty = tid >> 4, tx = tid & 15;
    const size_t base = ((size_t)b * NN) * DD + h * DH;
    const int n0s = ns * 512;

    const int lrow = tid >> 3;      // 0..31
    const int lch  = tid & 7;       // 0..7 (8 halves each)

    for (int n0 = n0s; n0 < n0s + 512; n0 += 32) {
        const size_t roff = base + (size_t)(n0 + lrow) * DD + lch * 8;
        const uint4 qv = *(const uint4*)(qf + roff);
        const uint4 kv = *(const uint4*)(kf + roff);
        {
            float2 f0 = __half22float2(*(const __half2*)&qv.x);
            float2 f1 = __half22float2(*(const __half2*)&qv.y);
            float2 f2 = __half22float2(*(const __half2*)&qv.z);
            float2 f3 = __half22float2(*(const __half2*)&qv.w);
            float4 a; a.x = f0.x; a.y = f0.y; a.z = f1.x; a.w = f1.y;
            float4 c; c.x = f2.x; c.y = f2.y; c.z = f3.x; c.w = f3.y;
            *(float4*)&Qs[lrow][lch * 8] = a;
            *(float4*)&Qs[lrow][lch * 8 + 4] = c;
        }
        {
            float2 f0 = __half22float2(*(const __half2*)&kv.x);
            float2 f1 = __half22float2(*(const __half2*)&kv.y);
            float2 f2 = __half22float2(*(const __half2*)&kv.z);
            float2 f3 = __half22float2(*(const __half2*)&kv.w);
            float4 a; a.x = f0.x; a.y = f0.y; a.z = f1.x; a.w = f1.y;
            float4 c; c.x = f2.x; c.y = f2.y; c.z = f3.x; c.w = f3.y;
            *(float4*)&Ks[lrow][lch * 8] = a;
            *(float4*)&Ks[lrow][lch * 8 + 4] = c;
        }
        __syncthreads();
#pragma unroll
        for (int kk = 0; kk < 32; kk++) {
            float qr[4], kr[4];
#pragma unroll
            for (int i = 0; i < 4; i++) qr[i] = Qs[kk][ty * 4 + i];
#pragma unroll
            for (int j = 0; j < 4; j++) kr[j] = Ks[kk][tx * 4 + j];
#pragma unroll
            for (int i = 0; i < 4; i++)
#pragma unroll
                for (int j = 0; j < 4; j++) acc[i][j] += qr[i] * kr[j];
        }
        __syncthreads();
    }

    float* Gout = Gpart + ((size_t)bh * 8 + ns) * (DH * DH);
#pragma unroll
    for (int i = 0; i < 4; i++)
#pragma unroll
        for (int j = 0; j < 4; j++)
            Gout[(ty * 4 + i) * DH + tx * 4 + j] = acc[i][j];
}

__global__ void __launch_bounds__(256) weights_kernel(
    const float* __restrict__ Gpart, float* __restrict__ Wt)
{
    const int bh = blockIdx.x;
    const int tid = threadIdx.x;
    __shared__ float Gs[DH][DH];
    __shared__ float ct[DH], st[DH];

    for (int e = tid; e < DH * DH; e += 256) {
        float sacc = 0.0f;
#pragma unroll
        for (int p = 0; p < 8; p++)
            sacc += Gpart[((size_t)bh * 8 + p) * (DH * DH) + e];
        Gs[e >> 6][e & 63] = sacc;
    }
    if (tid < DH) {
        float a = 6.283185307179586f * (float)tid / 64.0f;
        ct[tid] = cosf(a);
        st[tid] = sinf(a);
    }
    __syncthreads();

    const int i = tid >> 2;
    const int j0 = (tid & 3) * 16;
    for (int jj = 0; jj < 16; jj++) {
        const int j = j0 + jj;
        float re = 0.0f, im = 0.0f;
#pragma unroll
        for (int kk = 0; kk < DH; kk++) {
            const int t = (kk * j) & 63;
            const float g = Gs[i][kk];
            re += g * ct[t];
            im += g * st[t];
        }
        Wt[(size_t)bh * (DH * DH) + i * DH + j] = sqrtf(re * re + im * im);
    }
}

// attnpre = weights @ v per (b,h); fp16 v in, fp16 out
__global__ void __launch_bounds__(256) applyw_kernel(
    const __half* __restrict__ vf, const float* __restrict__ Wt,
    __half* __restrict__ ohf)
{
    const int bh = blockIdx.x;
    const int b = bh >> 4, h = bh & 15;
    const int tid = threadIdx.x;
    __shared__ float Ws[DH][DH + 1];
    __shared__ float Vs[4][DH];

    for (int e = tid; e < DH * DH; e += 256)
        Ws[e >> 6][e & 63] = Wt[(size_t)bh * (DH * DH) + e];
    __syncthreads();

    const int nn = tid >> 6;
    const int i = tid & 63;
    const size_t base = ((size_t)b * NN) * DD + h * DH;
    const int n0 = blockIdx.y * 64;

    for (int n = n0; n < n0 + 64; n += 4) {
        Vs[nn][i] = __half2float(vf[base + (size_t)(n + nn) * DD + i]);
        __syncthreads();
        float acc = 0.0f;
#pragma unroll
        for (int j = 0; j < DH; j++) acc += Ws[i][j] * Vs[nn][j];
        ohf[base + (size_t)(n + nn) * DD + i] = __float2half(acc);
        __syncthreads();
    }
}

// ===================== reduction finalize + norm =====================
__global__ void __launch_bounds__(256) red2_kernel(int nb)
{
    double a = 0.0, b = 0.0;
    for (int i = threadIdx.x; i < nb; i += 256) { a += g_part[i][0]; b += g_part[i][1]; }
    __shared__ double sa[256], sb[256];
    sa[threadIdx.x] = a;
    sb[threadIdx.x] = b;
    __syncthreads();
    for (int o = 128; o > 0; o >>= 1) {
        if (threadIdx.x < o) { sa[threadIdx.x] += sa[threadIdx.x + o]; sb[threadIdx.x] += sb[threadIdx.x + o]; }
        __syncthreads();
    }
    if (threadIdx.x == 0) { g_red[0] = sa[0]; g_red[1] = sb[0]; }
}

template <int OUTK> // 0 = fp32 only, 2 = also fp16
__global__ void __launch_bounds__(256) norm_kernel(
    const float* __restrict__ x, const float* __restrict__ alpha,
    const float* __restrict__ beta, const float* __restrict__ eps,
    float* __restrict__ y, __half* __restrict__ yh, size_t n)
{
    const double Md = (double)n;
    const double mean = g_red[0] / Md;
    const double var = (g_red[1] - Md * mean * mean) / (Md - 1.0);
    const float sd = (float)sqrt(var);

    const size_t n4 = n >> 2;
    const size_t stride = (size_t)gridDim.x * blockDim.x;
    for (size_t i4 = (size_t)blockIdx.x * blockDim.x + threadIdx.x; i4 < n4; i4 += stride) {
        float4 v = ((const float4*)x)[i4];
        const int d = (int)((i4 * 4) & (DD - 1));
        v.x = v.x / (sd + eps[d + 0]) * alpha[d + 0] + beta[d + 0];
        v.y = v.y / (sd + eps[d + 1]) * alpha[d + 1] + beta[d + 1];
        v.z = v.z / (sd + eps[d + 2]) * alpha[d + 2] + beta[d + 2];
        v.w = v.w / (sd + eps[d + 3]) * alpha[d + 3] + beta[d + 3];
        ((float4*)y)[i4] = v;
        if (OUTK == 2) {
            ((__half2*)yh)[i4 * 2 + 0] = __floats2half2_rn(v.x, v.y);
            ((__half2*)yh)[i4 * 2 + 1] = __floats2half2_rn(v.z, v.w);
        }
    }
}

// ===================== launch =====================
extern "C" void kernel_launch(void* const* d_in, const int* in_sizes, int n_in,
                              void* d_out, int out_size)
{
    const float* x    = (const float*)d_in[0];
    const float* wq_w = (const float*)d_in[1];
    const float* wq_b = (const float*)d_in[2];
    const float* wk_w = (const float*)d_in[3];
    const float* wk_b = (const float*)d_in[4];
    const float* wv_w = (const float*)d_in[5];
    const float* wv_b = (const float*)d_in[6];
    const float* wo_w = (const float*)d_in[7];
    const float* wo_b = (const float*)d_in[8];
    const float* w1   = (const float*)d_in[9];
    const float* b1   = (const float*)d_in[10];
    const float* w2   = (const float*)d_in[11];
    const float* b2   = (const float*)d_in[12];
    const float* an_a = (const float*)d_in[13];
    const float* an_b = (const float*)d_in[14];
    const float* an_e = (const float*)d_in[15];
    const float* mn_a = (const float*)d_in[16];
    const float* mn_b = (const float*)d_in[17];
    const float* mn_e = (const float*)d_in[18];
    float* out = (float*)d_out;

    float *attn, *out1, *Gpart, *Wt;
    cudaGetSymbolAddress((void**)&attn, g_attn);
    cudaGetSymbolAddress((void**)&out1, g_out1);
    cudaGetSymbolAddress((void**)&Gpart, g_Gpart);
    cudaGetSymbolAddress((void**)&Wt, g_Wt);

    __half *xf, *qf, *kf, *vf, *apf, *wqf, *wkf, *wvf, *wof, *w1f, *w2f, *atf, *hf;
    cudaGetSymbolAddress((void**)&xf, g_xf);
    cudaGetSymbolAddress((void**)&qf, g_qf);
    cudaGetSymbolAddress((void**)&kf, g_kf);
    cudaGetSymbolAddress((void**)&vf, g_vf);
    cudaGetSymbolAddress((void**)&apf, g_apf);
    cudaGetSymbolAddress((void**)&wqf, g_wqf);
    cudaGetSymbolAddress((void**)&wkf, g_wkf);
    cudaGetSymbolAddress((void**)&wvf, g_wvf);
    cudaGetSymbolAddress((void**)&wof, g_wof);
    cudaGetSymbolAddress((void**)&w1f, g_w1f);
    cudaGetSymbolAddress((void**)&w2f, g_w2f);
    cudaGetSymbolAddress((void**)&atf, g_atf);
    cudaGetSymbolAddress((void**)&hf, g_hf);

    cudaFuncSetAttribute(gemm_f16<false, false, true,  false>, cudaFuncAttributeMaxDynamicSharedMemorySize, F16_SMEM);
    cudaFuncSetAttribute(gemm_f16<true,  false, false, true >, cudaFuncAttributeMaxDynamicSharedMemorySize, F16_SMEM);
    cudaFuncSetAttribute(gemm_f16<false, true,  true,  false>, cudaFuncAttributeMaxDynamicSharedMemorySize, F16_SMEM);

    // ---- one merged conversion launch (x + all weights) ----
    cvt_all_kernel<<<2048, 256>>>(x, wq_w, wk_w, wv_w, wo_w, w1, w2,
                                  xf, wqf, wkf, wvf, wof, w1f, w2f);

    const dim3 gProj(DD / GW_BN, MM / GW_BM);   // (8, 128)
    const dim3 gMlp1(FF / GW_BN, MM / GW_BM);   // (32, 128)

    // ---- Q/K/V projections (fp16 out) ----
    gemm_f16<false, false, true, false><<<gProj, 256, F16_SMEM>>>(xf, wqf, wq_b, nullptr, nullptr, qf, MM, DD, DD);
    gemm_f16<false, false, true, false><<<gProj, 256, F16_SMEM>>>(xf, wkf, wk_b, nullptr, nullptr, kf, MM, DD, DD);
    gemm_f16<false, false, true, false><<<gProj, 256, F16_SMEM>>>(xf, wvf, wv_b, nullptr, nullptr, vf, MM, DD, DD);

    // ---- FFT attention (collapsed form) ----
    gram_kernel<<<dim3(BB * HH, 8), 256>>>(qf, kf, Gpart);
    weights_kernel<<<BB * HH, 256>>>(Gpart, Wt);
    applyw_kernel<<<dim3(BB * HH, NN / 64), 256>>>(vf, Wt, apf);

    // ---- output projection + residual (fp32 out), fused sum/sumsq ----
    gemm_f16<true, false, false, true><<<gProj, 256, F16_SMEM>>>(apf, wof, wo_b, x, attn, nullptr, MM, DD, DD);

    // ---- rmsnorm 1 (global std from fused partials), fp32 + fp16 outputs ----
    red2_kernel<<<1, 256>>>(1024);
    norm_kernel<2><<<2048, 256>>>(attn, an_a, an_b, an_e, attn, atf, TOT);

    // ---- MLP (fp16) ----
    gemm_f16<false, true, true, false><<<gMlp1, 256, F16_SMEM>>>(atf, w1f, b1, nullptr, nullptr, hf, MM, FF, DD);
    gemm_f16<true, false, false, true><<<gProj, 256, F16_SMEM>>>(hf, w2f, b2, attn, out1, nullptr, MM, DD, FF);

    // ---- rmsnorm 2 -> final fp32 output ----
    red2_kernel<<<1, 256>>>(1024);
    norm_kernel<0><<<2048, 256>>>(out1, mn_a, mn_b, mn_e, out, nullptr, TOT);
}

// round 14
// speedup vs baseline: 1.0296x; 1.0175x over previous
#include <cuda_runtime.h>
#include <cuda_fp16.h>
#include <cstdint>
#include <math.h>

// Problem dims (fixed by the dataset)
#define BB 4
#define NN 4096
#define DD 1024
#define HH 16
#define DH 64
#define FF 4096
#define MM (BB * NN)          // 16384
#define TOT ((size_t)MM * DD) // 16,777,216

// ===================== helpers =====================
__device__ __forceinline__ uint32_t smem_u32(const void* p) {
    uint32_t a;
    asm("{ .reg .u64 t; cvta.to.shared.u64 t, %1; cvt.u32.u64 %0, t; }" : "=r"(a) : "l"(p));
    return a;
}
__device__ __forceinline__ void cp_async16(uint32_t dst, const void* src) {
    asm volatile("cp.async.cg.shared.global [%0], [%1], 16;"
                 :: "r"(dst), "l"(__cvta_generic_to_global(src)));
}
__device__ __forceinline__ void cp_commit() { asm volatile("cp.async.commit_group;" ::: "memory"); }
__device__ __forceinline__ void cp_wait0()  { asm volatile("cp.async.wait_group 0;" ::: "memory"); }
__device__ __forceinline__ void cp_wait1()  { asm volatile("cp.async.wait_group 1;" ::: "memory"); }

#define MMAF16(d, a, b0, b1) \
    asm volatile("mma.sync.aligned.m16n8k16.row.col.f32.f16.f16.f32 " \
        "{%0,%1,%2,%3}, {%4,%5,%6,%7}, {%8,%9}, {%0,%1,%2,%3};" \
        : "+f"((d)[0]), "+f"((d)[1]), "+f"((d)[2]), "+f"((d)[3]) \
        : "r"((a)[0]), "r"((a)[1]), "r"((a)[2]), "r"((a)[3]), "r"(b0), "r"(b1))

#define LDMX4(r, addr) \
    asm volatile("ldmatrix.sync.aligned.m8n8.x4.shared.b16 {%0,%1,%2,%3}, [%4];" \
        : "=r"((r)[0]), "=r"((r)[1]), "=r"((r)[2]), "=r"((r)[3]) : "r"(addr))

// ===================== scratch (static device globals) =====================
__device__ float g_attn[MM * DD];
__device__ float g_out1[MM * DD];
__device__ float g_Gpart[BB * HH * 8 * DH * DH];
__device__ float g_Wt[BB * HH * DH * DH];
__device__ double g_part[4096][2];
__device__ double g_red[2];

// fp16 operands
__device__ __half g_xf[MM * DD];
__device__ __half g_qf[MM * DD];
__device__ __half g_kf[MM * DD];
__device__ __half g_vf[MM * DD];
__device__ __half g_apf[MM * DD];          // attnpre (weighted V)
__device__ __half g_wqf[DD * DD];
__device__ __half g_wkf[DD * DD];
__device__ __half g_wvf[DD * DD];
__device__ __half g_wof[DD * DD];
__device__ __half g_w1f[FF * DD];
__device__ __half g_w2f[DD * FF];
__device__ __half g_atf[MM * DD];
__device__ __half g_hf[(size_t)MM * FF];

// ===================== merged fp32 -> fp16 convert (x + all weights) ==========
__global__ void __launch_bounds__(256) cvt_all_kernel(
    const float* __restrict__ x,  const float* __restrict__ wq,
    const float* __restrict__ wk, const float* __restrict__ wv,
    const float* __restrict__ wo, const float* __restrict__ w1,
    const float* __restrict__ w2,
    __half* __restrict__ xf,  __half* __restrict__ wqf,
    __half* __restrict__ wkf, __half* __restrict__ wvf,
    __half* __restrict__ wof, __half* __restrict__ w1f,
    __half* __restrict__ w2f)
{
    const size_t SX = TOT / 4;
    const size_t SW = (size_t)DD * DD / 4;
    const size_t SF = (size_t)FF * DD / 4;
    const size_t e0 = SX;
    const size_t e1 = e0 + SW;
    const size_t e2 = e1 + SW;
    const size_t e3 = e2 + SW;
    const size_t e4 = e3 + SW;
    const size_t e5 = e4 + SF;
    const size_t e6 = e5 + SF;
    const size_t stride = (size_t)gridDim.x * blockDim.x;
    for (size_t i = (size_t)blockIdx.x * blockDim.x + threadIdx.x; i < e6; i += stride) {
        const float* s; __half* d; size_t off;
        if (i < e0)      { s = x;  d = xf;  off = i; }
        else if (i < e1) { s = wq; d = wqf; off = i - e0; }
        else if (i < e2) { s = wk; d = wkf; off = i - e1; }
        else if (i < e3) { s = wv; d = wvf; off = i - e2; }
        else if (i < e4) { s = wo; d = wof; off = i - e3; }
        else if (i < e5) { s = w1; d = w1f; off = i - e4; }
        else             { s = w2; d = w2f; off = i - e5; }
        float4 v = ((const float4*)s)[off];
        ((__half2*)d)[off * 2 + 0] = __floats2half2_rn(v.x, v.y);
        ((__half2*)d)[off * 2 + 1] = __floats2half2_rn(v.z, v.w);
    }
}

// ===================== fp16 single-product HMMA GEMM =====================
#define GW_BM 128
#define GW_BN 128
#define GW_BK 32
#define ROWB 80
#define BUFB (128 * ROWB)
#define F16_STAGEB (2 * BUFB)          // 20480 per stage (A + B)
#define NSTAGE 3
#define F16_SMEM (NSTAGE * F16_STAGEB) // 61440

template <bool HAS_RES, bool GELU, bool OUTF16, bool DO_RED>
__global__ void __launch_bounds__(256, 2) gemm_f16(
    const __half* __restrict__ A, const __half* __restrict__ B,
    const float* __restrict__ bias, const float* __restrict__ res,
    float* __restrict__ Cf, __half* __restrict__ Ch,
    int M, int N, int K)
{
    extern __shared__ char sm[];
    const int tid = threadIdx.x;
    const int wid = tid >> 5;
    const int lane = tid & 31;
    const int wm = wid & 3;
    const int wn = wid >> 2;
    const int bm = blockIdx.y * GW_BM;
    const int bn = blockIdx.x * GW_BN;
    const int KT = K / GW_BK;
    const uint32_t smb = smem_u32(sm);

    auto load_stage = [&](int kt) {
        const uint32_t sb = smb + (uint32_t)(kt % NSTAGE) * F16_STAGEB;
        const int k0 = kt * GW_BK;
#pragma unroll
        for (int i = 0; i < 4; i++) {
            const int c = tid + i * 256;
            const int buf = c >> 9;
            const int cc = c & 511;
            const int row = cc >> 2;
            const int qq = cc & 3;
            const __half* gb = buf ? B : A;
            const int grow = (buf ? bn : bm) + row;
            const void* src = gb + (size_t)grow * K + k0 + qq * 8;
            cp_async16(sb + buf * BUFB + row * ROWB + qq * 16, src);
        }
    };

    float acc[2][8][4];
#pragma unroll
    for (int mt = 0; mt < 2; mt++)
#pragma unroll
        for (int nt = 0; nt < 8; nt++)
#pragma unroll
            for (int r = 0; r < 4; r++) acc[mt][nt][r] = 0.0f;

    load_stage(0);
    cp_commit();
    if (KT > 1) { load_stage(1); cp_commit(); }

    const int lr = lane & 7;
    const int a_row = wm * 32 + lr + ((lane & 8) ? 8 : 0);
    const int a_kb  = (lane & 16) ? 16 : 0;
    const int b_row = wn * 64 + lr + ((lane & 16) ? 8 : 0);
    const int b_kb  = (lane & 8) ? 16 : 0;

    for (int kt = 0; kt < KT; kt++) {
        if (kt + 1 < KT) cp_wait1(); else cp_wait0();
        __syncthreads();   // single barrier per kt: rendezvous for both data-ready and buffer-free

        if (kt + 2 < KT) {
            load_stage(kt + 2);
            cp_commit();
        }

        const uint32_t sb = smb + (uint32_t)(kt % NSTAGE) * F16_STAGEB;
        const uint32_t As = sb;
        const uint32_t Bs = sb + BUFB;

#pragma unroll
        for (int k16 = 0; k16 < 2; k16++) {
            const int kc = k16 * 32;
            uint32_t af[2][4];
            uint32_t bf[4][4];
#pragma unroll
            for (int mt = 0; mt < 2; mt++)
                LDMX4(af[mt], As + (uint32_t)((a_row + mt * 16) * ROWB + kc + a_kb));
#pragma unroll
            for (int p = 0; p < 4; p++)
                LDMX4(bf[p], Bs + (uint32_t)((b_row + p * 16) * ROWB + kc + b_kb));
#pragma unroll
            for (int p = 0; p < 4; p++)
#pragma unroll
                for (int sub = 0; sub < 2; sub++) {
                    const int nt = p * 2 + sub;
#pragma unroll
                    for (int mt = 0; mt < 2; mt++)
                        MMAF16(acc[mt][nt], af[mt], bf[p][sub * 2], bf[p][sub * 2 + 1]);
                }
        }
        // no trailing sync: next iteration's top barrier provides the rendezvous
    }

    float rs = 0.0f, rs2 = 0.0f;

#pragma unroll
    for (int mt = 0; mt < 2; mt++) {
        const int r0 = bm + wm * 32 + mt * 16 + (lane >> 2);
#pragma unroll
        for (int nt = 0; nt < 8; nt++) {
            const int c = bn + wn * 64 + nt * 8 + ((lane & 3) << 1);
            const float b0 = bias[c], b1 = bias[c + 1];
#pragma unroll
            for (int half = 0; half < 2; half++) {
                const int row = r0 + half * 8;
                float v0 = acc[mt][nt][half * 2 + 0] + b0;
                float v1 = acc[mt][nt][half * 2 + 1] + b1;
                if (HAS_RES) {
                    const float2 rr = *(const float2*)(res + (size_t)row * N + c);
                    v0 += rr.x; v1 += rr.y;
                }
                if (GELU) {
                    v0 = 0.5f * v0 * (1.0f + erff(v0 * 0.70710678118654752f));
                    v1 = 0.5f * v1 * (1.0f + erff(v1 * 0.70710678118654752f));
                }
                if (DO_RED) {
                    rs += v0 + v1;
                    rs2 += v0 * v0 + v1 * v1;
                }
                if (OUTF16) {
                    *(__half2*)(Ch + (size_t)row * N + c) = __floats2half2_rn(v0, v1);
                } else {
                    float2 o; o.x = v0; o.y = v1;
                    *(float2*)(Cf + (size_t)row * N + c) = o;
                }
            }
        }
    }

    if (DO_RED) {
#pragma unroll
        for (int o = 16; o > 0; o >>= 1) {
            rs += __shfl_down_sync(0xFFFFFFFFu, rs, o);
            rs2 += __shfl_down_sync(0xFFFFFFFFu, rs2, o);
        }
        __shared__ float shr[2][8];
        if (lane == 0) { shr[0][wid] = rs; shr[1][wid] = rs2; }
        __syncthreads();
        if (tid == 0) {
            double a = 0.0, b = 0.0;
#pragma unroll
            for (int i = 0; i < 8; i++) { a += (double)shr[0][i]; b += (double)shr[1][i]; }
            const int cid = blockIdx.y * gridDim.x + blockIdx.x;
            g_part[cid][0] = a;
            g_part[cid][1] = b;
        }
    }
}

// ===================== attention small ops =====================
__global__ void __launch_bounds__(256) gram_kernel(
    const __half* __restrict__ qf, const __half* __restrict__ kf,
    float* __restrict__ Gpart)
{
    const int bh = blockIdx.x;
    const int ns = blockIdx.y;
    const int b = bh >> 4, h = bh & 15;
    const int tid = threadIdx.x;
    __shared__ float Qs[32][68];
    __shared__ float Ks[32][68];

    float acc[4][4];
#pragma unroll
    for (int i = 0; i < 4; i++)
#pragma unroll
        for (int j = 0; j < 4; j++) acc[i][j] = 0.0f;

    const int ty = tid >> 4, tx = tid & 15;
    const size_t base = ((size_t)b * NN) * DD + h * DH;
    const int n0s = ns * 512;

    const int lrow = tid >> 3;
    const int lch  = tid & 7;

    for (int n0 = n0s; n0 < n0s + 512; n0 += 32) {
        const size_t roff = base + (size_t)(n0 + lrow) * DD + lch * 8;
        const uint4 qv = *(const uint4*)(qf + roff);
        const uint4 kv = *(const uint4*)(kf + roff);
        {
            float2 f0 = __half22float2(*(const __half2*)&qv.x);
            float2 f1 = __half22float2(*(const __half2*)&qv.y);
            float2 f2 = __half22float2(*(const __half2*)&qv.z);
            float2 f3 = __half22float2(*(const __half2*)&qv.w);
            float4 a; a.x = f0.x; a.y = f0.y; a.z = f1.x; a.w = f1.y;
            float4 c; c.x = f2.x; c.y = f2.y; c.z = f3.x; c.w = f3.y;
            *(float4*)&Qs[lrow][lch * 8] = a;
            *(float4*)&Qs[lrow][lch * 8 + 4] = c;
        }
        {
            float2 f0 = __half22float2(*(const __half2*)&kv.x);
            float2 f1 = __half22float2(*(const __half2*)&kv.y);
            float2 f2 = __half22float2(*(const __half2*)&kv.z);
            float2 f3 = __half22float2(*(const __half2*)&kv.w);
            float4 a; a.x = f0.x; a.y = f0.y; a.z = f1.x; a.w = f1.y;
            float4 c; c.x = f2.x; c.y = f2.y; c.z = f3.x; c.w = f3.y;
            *(float4*)&Ks[lrow][lch * 8] = a;
            *(float4*)&Ks[lrow][lch * 8 + 4] = c;
        }
        __syncthreads();
#pragma unroll
        for (int kk = 0; kk < 32; kk++) {
            float qr[4], kr[4];
#pragma unroll
            for (int i = 0; i < 4; i++) qr[i] = Qs[kk][ty * 4 + i];
#pragma unroll
            for (int j = 0; j < 4; j++) kr[j] = Ks[kk][tx * 4 + j];
#pragma unroll
            for (int i = 0; i < 4; i++)
#pragma unroll
                for (int j = 0; j < 4; j++) acc[i][j] += qr[i] * kr[j];
        }
        __syncthreads();
    }

    float* Gout = Gpart + ((size_t)bh * 8 + ns) * (DH * DH);
#pragma unroll
    for (int i = 0; i < 4; i++)
#pragma unroll
        for (int j = 0; j < 4; j++)
            Gout[(ty * 4 + i) * DH + tx * 4 + j] = acc[i][j];
}

__global__ void __launch_bounds__(256) weights_kernel(
    const float* __restrict__ Gpart, float* __restrict__ Wt)
{
    const int bh = blockIdx.x;
    const int tid = threadIdx.x;
    __shared__ float Gs[DH][DH];
    __shared__ float ct[DH], st[DH];

    for (int e = tid; e < DH * DH; e += 256) {
        float sacc = 0.0f;
#pragma unroll
        for (int p = 0; p < 8; p++)
            sacc += Gpart[((size_t)bh * 8 + p) * (DH * DH) + e];
        Gs[e >> 6][e & 63] = sacc;
    }
    if (tid < DH) {
        float a = 6.283185307179586f * (float)tid / 64.0f;
        ct[tid] = cosf(a);
        st[tid] = sinf(a);
    }
    __syncthreads();

    const int i = tid >> 2;
    const int j0 = (tid & 3) * 16;
    for (int jj = 0; jj < 16; jj++) {
        const int j = j0 + jj;
        float re = 0.0f, im = 0.0f;
#pragma unroll
        for (int kk = 0; kk < DH; kk++) {
            const int t = (kk * j) & 63;
            const float g = Gs[i][kk];
            re += g * ct[t];
            im += g * st[t];
        }
        Wt[(size_t)bh * (DH * DH) + i * DH + j] = sqrtf(re * re + im * im);
    }
}

__global__ void __launch_bounds__(256) applyw_kernel(
    const __half* __restrict__ vf, const float* __restrict__ Wt,
    __half* __restrict__ ohf)
{
    const int bh = blockIdx.x;
    const int b = bh >> 4, h = bh & 15;
    const int tid = threadIdx.x;
    __shared__ float Ws[DH][DH + 1];
    __shared__ float Vs[4][DH];

    for (int e = tid; e < DH * DH; e += 256)
        Ws[e >> 6][e & 63] = Wt[(size_t)bh * (DH * DH) + e];
    __syncthreads();

    const int nn = tid >> 6;
    const int i = tid & 63;
    const size_t base = ((size_t)b * NN) * DD + h * DH;
    const int n0 = blockIdx.y * 64;

    for (int n = n0; n < n0 + 64; n += 4) {
        Vs[nn][i] = __half2float(vf[base + (size_t)(n + nn) * DD + i]);
        __syncthreads();
        float acc = 0.0f;
#pragma unroll
        for (int j = 0; j < DH; j++) acc += Ws[i][j] * Vs[nn][j];
        ohf[base + (size_t)(n + nn) * DD + i] = __float2half(acc);
        __syncthreads();
    }
}

// ===================== reduction finalize + norm =====================
__global__ void __launch_bounds__(256) red2_kernel(int nb)
{
    double a = 0.0, b = 0.0;
    for (int i = threadIdx.x; i < nb; i += 256) { a += g_part[i][0]; b += g_part[i][1]; }
    __shared__ double sa[256], sb[256];
    sa[threadIdx.x] = a;
    sb[threadIdx.x] = b;
    __syncthreads();
    for (int o = 128; o > 0; o >>= 1) {
        if (threadIdx.x < o) { sa[threadIdx.x] += sa[threadIdx.x + o]; sb[threadIdx.x] += sb[threadIdx.x + o]; }
        __syncthreads();
    }
    if (threadIdx.x == 0) { g_red[0] = sa[0]; g_red[1] = sb[0]; }
}

template <int OUTK> // 0 = fp32 only, 2 = also fp16
__global__ void __launch_bounds__(256) norm_kernel(
    const float* __restrict__ x, const float* __restrict__ alpha,
    const float* __restrict__ beta, const float* __restrict__ eps,
    float* __restrict__ y, __half* __restrict__ yh, size_t n)
{
    const double Md = (double)n;
    const double mean = g_red[0] / Md;
    const double var = (g_red[1] - Md * mean * mean) / (Md - 1.0);
    const float sd = (float)sqrt(var);

    const size_t n4 = n >> 2;
    const size_t stride = (size_t)gridDim.x * blockDim.x;
    for (size_t i4 = (size_t)blockIdx.x * blockDim.x + threadIdx.x; i4 < n4; i4 += stride) {
        float4 v = ((const float4*)x)[i4];
        const int d = (int)((i4 * 4) & (DD - 1));
        v.x = v.x / (sd + eps[d + 0]) * alpha[d + 0] + beta[d + 0];
        v.y = v.y / (sd + eps[d + 1]) * alpha[d + 1] + beta[d + 1];
        v.z = v.z / (sd + eps[d + 2]) * alpha[d + 2] + beta[d + 2];
        v.w = v.w / (sd + eps[d + 3]) * alpha[d + 3] + beta[d + 3];
        ((float4*)y)[i4] = v;
        if (OUTK == 2) {
            ((__half2*)yh)[i4 * 2 + 0] = __floats2half2_rn(v.x, v.y);
            ((__half2*)yh)[i4 * 2 + 1] = __floats2half2_rn(v.z, v.w);
        }
    }
}

// ===================== launch =====================
extern "C" void kernel_launch(void* const* d_in, const int* in_sizes, int n_in,
                              void* d_out, int out_size)
{
    const float* x    = (const float*)d_in[0];
    const float* wq_w = (const float*)d_in[1];
    const float* wq_b = (const float*)d_in[2];
    const float* wk_w = (const float*)d_in[3];
    const float* wk_b = (const float*)d_in[4];
    const float* wv_w = (const float*)d_in[5];
    const float* wv_b = (const float*)d_in[6];
    const float* wo_w = (const float*)d_in[7];
    const float* wo_b = (const float*)d_in[8];
    const float* w1   = (const float*)d_in[9];
    const float* b1   = (const float*)d_in[10];
    const float* w2   = (const float*)d_in[11];
    const float* b2   = (const float*)d_in[12];
    const float* an_a = (const float*)d_in[13];
    const float* an_b = (const float*)d_in[14];
    const float* an_e = (const float*)d_in[15];
    const float* mn_a = (const float*)d_in[16];
    const float* mn_b = (const float*)d_in[17];
    const float* mn_e = (const float*)d_in[18];
    float* out = (float*)d_out;

    float *attn, *out1, *Gpart, *Wt;
    cudaGetSymbolAddress((void**)&attn, g_attn);
    cudaGetSymbolAddress((void**)&out1, g_out1);
    cudaGetSymbolAddress((void**)&Gpart, g_Gpart);
    cudaGetSymbolAddress((void**)&Wt, g_Wt);

    __half *xf, *qf, *kf, *vf, *apf, *wqf, *wkf, *wvf, *wof, *w1f, *w2f, *atf, *hf;
    cudaGetSymbolAddress((void**)&xf, g_xf);
    cudaGetSymbolAddress((void**)&qf, g_qf);
    cudaGetSymbolAddress((void**)&kf, g_kf);
    cudaGetSymbolAddress((void**)&vf, g_vf);
    cudaGetSymbolAddress((void**)&apf, g_apf);
    cudaGetSymbolAddress((void**)&wqf, g_wqf);
    cudaGetSymbolAddress((void**)&wkf, g_wkf);
    cudaGetSymbolAddress((void**)&wvf, g_wvf);
    cudaGetSymbolAddress((void**)&wof, g_wof);
    cudaGetSymbolAddress((void**)&w1f, g_w1f);
    cudaGetSymbolAddress((void**)&w2f, g_w2f);
    cudaGetSymbolAddress((void**)&atf, g_atf);
    cudaGetSymbolAddress((void**)&hf, g_hf);

    cudaFuncSetAttribute(gemm_f16<false, false, true,  false>, cudaFuncAttributeMaxDynamicSharedMemorySize, F16_SMEM);
    cudaFuncSetAttribute(gemm_f16<true,  false, false, true >, cudaFuncAttributeMaxDynamicSharedMemorySize, F16_SMEM);
    cudaFuncSetAttribute(gemm_f16<false, true,  true,  false>, cudaFuncAttributeMaxDynamicSharedMemorySize, F16_SMEM);

    // ---- one merged conversion launch (x + all weights) ----
    cvt_all_kernel<<<2048, 256>>>(x, wq_w, wk_w, wv_w, wo_w, w1, w2,
                                  xf, wqf, wkf, wvf, wof, w1f, w2f);

    const dim3 gProj(DD / GW_BN, MM / GW_BM);   // (8, 128)
    const dim3 gMlp1(FF / GW_BN, MM / GW_BM);   // (32, 128)

    // ---- Q/K/V projections (fp16 out) ----
    gemm_f16<false, false, true, false><<<gProj, 256, F16_SMEM>>>(xf, wqf, wq_b, nullptr, nullptr, qf, MM, DD, DD);
    gemm_f16<false, false, true, false><<<gProj, 256, F16_SMEM>>>(xf, wkf, wk_b, nullptr, nullptr, kf, MM, DD, DD);
    gemm_f16<false, false, true, false><<<gProj, 256, F16_SMEM>>>(xf, wvf, wv_b, nullptr, nullptr, vf, MM, DD, DD);

    // ---- FFT attention (collapsed form) ----
    gram_kernel<<<dim3(BB * HH, 8), 256>>>(qf, kf, Gpart);
    weights_kernel<<<BB * HH, 256>>>(Gpart, Wt);
    applyw_kernel<<<dim3(BB * HH, NN / 64), 256>>>(vf, Wt, apf);

    // ---- output projection + residual (fp32 out), fused sum/sumsq ----
    gemm_f16<true, false, false, true><<<gProj, 256, F16_SMEM>>>(apf, wof, wo_b, x, attn, nullptr, MM, DD, DD);

    // ---- rmsnorm 1 (global std from fused partials), fp32 + fp16 outputs ----
    red2_kernel<<<1, 256>>>(1024);
    norm_kernel<2><<<2048, 256>>>(attn, an_a, an_b, an_e, attn, atf, TOT);

    // ---- MLP (fp16) ----
    gemm_f16<false, true, true, false><<<gMlp1, 256, F16_SMEM>>>(atf, w1f, b1, nullptr, nullptr, hf, MM, FF, DD);
    gemm_f16<true, false, false, true><<<gProj, 256, F16_SMEM>>>(hf, w2f, b2, attn, out1, nullptr, MM, DD, FF);

    // ---- rmsnorm 2 -> final fp32 output ----
    red2_kernel<<<1, 256>>>(1024);
    norm_kernel<0><<<2048, 256>>>(out1, mn_a, mn_b, mn_e, out, nullptr, TOT);
}

// round 15
// speedup vs baseline: 1.0320x; 1.0023x over previous
#include <cuda_runtime.h>
#include <cuda_fp16.h>
#include <cstdint>
#include <math.h>

// Problem dims (fixed by the dataset)
#define BB 4
#define NN 4096
#define DD 1024
#define HH 16
#define DH 64
#define FF 4096
#define MM (BB * NN)          // 16384
#define TOT ((size_t)MM * DD) // 16,777,216
#define QKVN (3 * DD)

// ===================== helpers =====================
__device__ __forceinline__ uint32_t smem_u32(const void* p) {
    uint32_t a;
    asm("{ .reg .u64 t; cvta.to.shared.u64 t, %1; cvt.u32.u64 %0, t; }" : "=r"(a) : "l"(p));
    return a;
}
__device__ __forceinline__ void cp_async16(uint32_t dst, const void* src) {
    asm volatile("cp.async.cg.shared.global [%0], [%1], 16;"
                 :: "r"(dst), "l"(__cvta_generic_to_global(src)));
}
__device__ __forceinline__ void cp_commit() { asm volatile("cp.async.commit_group;" ::: "memory"); }
__device__ __forceinline__ void cp_wait0()  { asm volatile("cp.async.wait_group 0;" ::: "memory"); }
__device__ __forceinline__ void cp_wait1()  { asm volatile("cp.async.wait_group 1;" ::: "memory"); }

#define MMAF16(d, a, b0, b1) \
    asm volatile("mma.sync.aligned.m16n8k16.row.col.f32.f16.f16.f32 " \
        "{%0,%1,%2,%3}, {%4,%5,%6,%7}, {%8,%9}, {%0,%1,%2,%3};" \
        : "+f"((d)[0]), "+f"((d)[1]), "+f"((d)[2]), "+f"((d)[3]) \
        : "r"((a)[0]), "r"((a)[1]), "r"((a)[2]), "r"((a)[3]), "r"(b0), "r"(b1))

#define LDMX4(r, addr) \
    asm volatile("ldmatrix.sync.aligned.m8n8.x4.shared.b16 {%0,%1,%2,%3}, [%4];" \
        : "=r"((r)[0]), "=r"((r)[1]), "=r"((r)[2]), "=r"((r)[3]) : "r"(addr))

// ===================== scratch (static device globals) =====================
__device__ float g_attn[MM * DD];
__device__ float g_out1[MM * DD];
__device__ float g_Gpart[BB * HH * 8 * DH * DH];
__device__ float g_Wt[BB * HH * DH * DH];
__device__ float g_bqkv[QKVN];
__device__ double g_part[4096][2];
__device__ double g_red[2];

// fp16 operands
__device__ __half g_xf[MM * DD];
__device__ __half g_qf[MM * DD];
__device__ __half g_kf[MM * DD];
__device__ __half g_vf[MM * DD];
__device__ __half g_apf[MM * DD];          // attnpre (weighted V)
__device__ __half g_wqkvf[3 * DD * DD];    // wq | wk | wv concatenated along N
__device__ __half g_wof[DD * DD];
__device__ __half g_w1f[FF * DD];
__device__ __half g_w2f[DD * FF];
__device__ __half g_atf[MM * DD];
__device__ __half g_hf[(size_t)MM * FF];

// ===================== merged fp32 -> fp16 convert (x + all weights) ==========
__global__ void __launch_bounds__(256) cvt_all_kernel(
    const float* __restrict__ x,  const float* __restrict__ wq,
    const float* __restrict__ wk, const float* __restrict__ wv,
    const float* __restrict__ wo, const float* __restrict__ w1,
    const float* __restrict__ w2,
    __half* __restrict__ xf,  __half* __restrict__ wqf,
    __half* __restrict__ wkf, __half* __restrict__ wvf,
    __half* __restrict__ wof, __half* __restrict__ w1f,
    __half* __restrict__ w2f)
{
    const size_t SX = TOT / 4;
    const size_t SW = (size_t)DD * DD / 4;
    const size_t SF = (size_t)FF * DD / 4;
    const size_t e0 = SX;
    const size_t e1 = e0 + SW;
    const size_t e2 = e1 + SW;
    const size_t e3 = e2 + SW;
    const size_t e4 = e3 + SW;
    const size_t e5 = e4 + SF;
    const size_t e6 = e5 + SF;
    const size_t stride = (size_t)gridDim.x * blockDim.x;
    for (size_t i = (size_t)blockIdx.x * blockDim.x + threadIdx.x; i < e6; i += stride) {
        const float* s; __half* d; size_t off;
        if (i < e0)      { s = x;  d = xf;  off = i; }
        else if (i < e1) { s = wq; d = wqf; off = i - e0; }
        else if (i < e2) { s = wk; d = wkf; off = i - e1; }
        else if (i < e3) { s = wv; d = wvf; off = i - e2; }
        else if (i < e4) { s = wo; d = wof; off = i - e3; }
        else if (i < e5) { s = w1; d = w1f; off = i - e4; }
        else             { s = w2; d = w2f; off = i - e5; }
        float4 v = ((const float4*)s)[off];
        ((__half2*)d)[off * 2 + 0] = __floats2half2_rn(v.x, v.y);
        ((__half2*)d)[off * 2 + 1] = __floats2half2_rn(v.z, v.w);
    }
}

// ===================== fp16 single-product HMMA GEMM =====================
#define GW_BM 128
#define GW_BN 128
#define GW_BK 32
#define ROWB 80
#define BUFB (128 * ROWB)
#define F16_STAGEB (2 * BUFB)          // 20480 per stage (A + B)
#define NSTAGE 3
#define F16_SMEM (NSTAGE * F16_STAGEB) // 61440

// OUT3: route fp16 output to one of {Ch, Ch2, Ch3} by bn>>10, each with row stride DD
template <bool HAS_RES, bool GELU, bool OUTF16, bool DO_RED, bool OUT3>
__global__ void __launch_bounds__(256, 2) gemm_f16(
    const __half* __restrict__ A, const __half* __restrict__ B,
    const float* __restrict__ bias, const float* __restrict__ res,
    float* __restrict__ Cf, __half* __restrict__ Ch,
    __half* __restrict__ Ch2, __half* __restrict__ Ch3,
    int M, int N, int K)
{
    extern __shared__ char sm[];
    const int tid = threadIdx.x;
    const int wid = tid >> 5;
    const int lane = tid & 31;
    const int wm = wid & 3;
    const int wn = wid >> 2;
    const int bm = blockIdx.y * GW_BM;
    const int bn = blockIdx.x * GW_BN;
    const int KT = K / GW_BK;
    const uint32_t smb = smem_u32(sm);

    auto load_stage = [&](int kt) {
        const uint32_t sb = smb + (uint32_t)(kt % NSTAGE) * F16_STAGEB;
        const int k0 = kt * GW_BK;
#pragma unroll
        for (int i = 0; i < 4; i++) {
            const int c = tid + i * 256;
            const int buf = c >> 9;
            const int cc = c & 511;
            const int row = cc >> 2;
            const int qq = cc & 3;
            const __half* gb = buf ? B : A;
            const int grow = (buf ? bn : bm) + row;
            const void* src = gb + (size_t)grow * K + k0 + qq * 8;
            cp_async16(sb + buf * BUFB + row * ROWB + qq * 16, src);
        }
    };

    float acc[2][8][4];
#pragma unroll
    for (int mt = 0; mt < 2; mt++)
#pragma unroll
        for (int nt = 0; nt < 8; nt++)
#pragma unroll
            for (int r = 0; r < 4; r++) acc[mt][nt][r] = 0.0f;

    load_stage(0);
    cp_commit();
    if (KT > 1) { load_stage(1); cp_commit(); }

    const int lr = lane & 7;
    const int a_row = wm * 32 + lr + ((lane & 8) ? 8 : 0);
    const int a_kb  = (lane & 16) ? 16 : 0;
    const int b_row = wn * 64 + lr + ((lane & 16) ? 8 : 0);
    const int b_kb  = (lane & 8) ? 16 : 0;

    for (int kt = 0; kt < KT; kt++) {
        if (kt + 1 < KT) cp_wait1(); else cp_wait0();
        __syncthreads();   // single barrier per kt

        if (kt + 2 < KT) {
            load_stage(kt + 2);
            cp_commit();
        }

        const uint32_t sb = smb + (uint32_t)(kt % NSTAGE) * F16_STAGEB;
        const uint32_t As = sb;
        const uint32_t Bs = sb + BUFB;

#pragma unroll
        for (int k16 = 0; k16 < 2; k16++) {
            const int kc = k16 * 32;
            uint32_t af[2][4];
            uint32_t bf[4][4];
#pragma unroll
            for (int mt = 0; mt < 2; mt++)
                LDMX4(af[mt], As + (uint32_t)((a_row + mt * 16) * ROWB + kc + a_kb));
#pragma unroll
            for (int p = 0; p < 4; p++)
                LDMX4(bf[p], Bs + (uint32_t)((b_row + p * 16) * ROWB + kc + b_kb));
#pragma unroll
            for (int p = 0; p < 4; p++)
#pragma unroll
                for (int sub = 0; sub < 2; sub++) {
                    const int nt = p * 2 + sub;
#pragma unroll
                    for (int mt = 0; mt < 2; mt++)
                        MMAF16(acc[mt][nt], af[mt], bf[p][sub * 2], bf[p][sub * 2 + 1]);
                }
        }
    }

    // output routing for OUT3 (uniform per CTA: bn is a multiple of 128)
    __half* Co = Ch;
    int cofs = 0;
    if (OUT3) {
        const int seg = bn >> 10;
        Co = (seg == 0) ? Ch : (seg == 1) ? Ch2 : Ch3;
        cofs = seg << 10;
    }

    float rs = 0.0f, rs2 = 0.0f;

#pragma unroll
    for (int mt = 0; mt < 2; mt++) {
        const int r0 = bm + wm * 32 + mt * 16 + (lane >> 2);
#pragma unroll
        for (int nt = 0; nt < 8; nt++) {
            const int c = bn + wn * 64 + nt * 8 + ((lane & 3) << 1);
            const float b0 = bias[c], b1 = bias[c + 1];
#pragma unroll
            for (int half = 0; half < 2; half++) {
                const int row = r0 + half * 8;
                float v0 = acc[mt][nt][half * 2 + 0] + b0;
                float v1 = acc[mt][nt][half * 2 + 1] + b1;
                if (HAS_RES) {
                    const float2 rr = *(const float2*)(res + (size_t)row * N + c);
                    v0 += rr.x; v1 += rr.y;
                }
                if (GELU) {
                    v0 = 0.5f * v0 * (1.0f + erff(v0 * 0.70710678118654752f));
                    v1 = 0.5f * v1 * (1.0f + erff(v1 * 0.70710678118654752f));
                }
                if (DO_RED) {
                    rs += v0 + v1;
                    rs2 += v0 * v0 + v1 * v1;
                }
                if (OUTF16) {
                    if (OUT3)
                        *(__half2*)(Co + (size_t)row * DD + (c - cofs)) = __floats2half2_rn(v0, v1);
                    else
                        *(__half2*)(Ch + (size_t)row * N + c) = __floats2half2_rn(v0, v1);
                } else {
                    float2 o; o.x = v0; o.y = v1;
                    *(float2*)(Cf + (size_t)row * N + c) = o;
                }
            }
        }
    }

    if (DO_RED) {
#pragma unroll
        for (int o = 16; o > 0; o >>= 1) {
            rs += __shfl_down_sync(0xFFFFFFFFu, rs, o);
            rs2 += __shfl_down_sync(0xFFFFFFFFu, rs2, o);
        }
        __shared__ float shr[2][8];
        if (lane == 0) { shr[0][wid] = rs; shr[1][wid] = rs2; }
        __syncthreads();
        if (tid == 0) {
            double a = 0.0, b = 0.0;
#pragma unroll
            for (int i = 0; i < 8; i++) { a += (double)shr[0][i]; b += (double)shr[1][i]; }
            const int cid = blockIdx.y * gridDim.x + blockIdx.x;
            g_part[cid][0] = a;
            g_part[cid][1] = b;
        }
    }
}

// ===================== attention small ops =====================
__global__ void __launch_bounds__(256) gram_kernel(
    const __half* __restrict__ qf, const __half* __restrict__ kf,
    float* __restrict__ Gpart)
{
    const int bh = blockIdx.x;
    const int ns = blockIdx.y;
    const int b = bh >> 4, h = bh & 15;
    const int tid = threadIdx.x;
    __shared__ float Qs[32][68];
    __shared__ float Ks[32][68];

    float acc[4][4];
#pragma unroll
    for (int i = 0; i < 4; i++)
#pragma unroll
        for (int j = 0; j < 4; j++) acc[i][j] = 0.0f;

    const int ty = tid >> 4, tx = tid & 15;
    const size_t base = ((size_t)b * NN) * DD + h * DH;
    const int n0s = ns * 512;

    const int lrow = tid >> 3;
    const int lch  = tid & 7;

    for (int n0 = n0s; n0 < n0s + 512; n0 += 32) {
        const size_t roff = base + (size_t)(n0 + lrow) * DD + lch * 8;
        const uint4 qv = *(const uint4*)(qf + roff);
        const uint4 kv = *(const uint4*)(kf + roff);
        {
            float2 f0 = __half22float2(*(const __half2*)&qv.x);
            float2 f1 = __half22float2(*(const __half2*)&qv.y);
            float2 f2 = __half22float2(*(const __half2*)&qv.z);
            float2 f3 = __half22float2(*(const __half2*)&qv.w);
            float4 a; a.x = f0.x; a.y = f0.y; a.z = f1.x; a.w = f1.y;
            float4 c; c.x = f2.x; c.y = f2.y; c.z = f3.x; c.w = f3.y;
            *(float4*)&Qs[lrow][lch * 8] = a;
            *(float4*)&Qs[lrow][lch * 8 + 4] = c;
        }
        {
            float2 f0 = __half22float2(*(const __half2*)&kv.x);
            float2 f1 = __half22float2(*(const __half2*)&kv.y);
            float2 f2 = __half22float2(*(const __half2*)&kv.z);
            float2 f3 = __half22float2(*(const __half2*)&kv.w);
            float4 a; a.x = f0.x; a.y = f0.y; a.z = f1.x; a.w = f1.y;
            float4 c; c.x = f2.x; c.y = f2.y; c.z = f3.x; c.w = f3.y;
            *(float4*)&Ks[lrow][lch * 8] = a;
            *(float4*)&Ks[lrow][lch * 8 + 4] = c;
        }
        __syncthreads();
#pragma unroll
        for (int kk = 0; kk < 32; kk++) {
            float qr[4], kr[4];
#pragma unroll
            for (int i = 0; i < 4; i++) qr[i] = Qs[kk][ty * 4 + i];
#pragma unroll
            for (int j = 0; j < 4; j++) kr[j] = Ks[kk][tx * 4 + j];
#pragma unroll
            for (int i = 0; i < 4; i++)
#pragma unroll
                for (int j = 0; j < 4; j++) acc[i][j] += qr[i] * kr[j];
        }
        __syncthreads();
    }

    float* Gout = Gpart + ((size_t)bh * 8 + ns) * (DH * DH);
#pragma unroll
    for (int i = 0; i < 4; i++)
#pragma unroll
        for (int j = 0; j < 4; j++)
            Gout[(ty * 4 + i) * DH + tx * 4 + j] = acc[i][j];
}

__global__ void __launch_bounds__(256) weights_kernel(
    const float* __restrict__ Gpart, float* __restrict__ Wt)
{
    const int bh = blockIdx.x;
    const int tid = threadIdx.x;
    __shared__ float Gs[DH][DH];
    __shared__ float ct[DH], st[DH];

    for (int e = tid; e < DH * DH; e += 256) {
        float sacc = 0.0f;
#pragma unroll
        for (int p = 0; p < 8; p++)
            sacc += Gpart[((size_t)bh * 8 + p) * (DH * DH) + e];
        Gs[e >> 6][e & 63] = sacc;
    }
    if (tid < DH) {
        float a = 6.283185307179586f * (float)tid / 64.0f;
        ct[tid] = cosf(a);
        st[tid] = sinf(a);
    }
    __syncthreads();

    const int i = tid >> 2;
    const int j0 = (tid & 3) * 16;
    for (int jj = 0; jj < 16; jj++) {
        const int j = j0 + jj;
        float re = 0.0f, im = 0.0f;
#pragma unroll
        for (int kk = 0; kk < DH; kk++) {
            const int t = (kk * j) & 63;
            const float g = Gs[i][kk];
            re += g * ct[t];
            im += g * st[t];
        }
        Wt[(size_t)bh * (DH * DH) + i * DH + j] = sqrtf(re * re + im * im);
    }
}

__global__ void __launch_bounds__(256) applyw_kernel(
    const __half* __restrict__ vf, const float* __restrict__ Wt,
    __half* __restrict__ ohf)
{
    const int bh = blockIdx.x;
    const int b = bh >> 4, h = bh & 15;
    const int tid = threadIdx.x;
    __shared__ float Ws[DH][DH + 1];
    __shared__ float Vs[4][DH];

    for (int e = tid; e < DH * DH; e += 256)
        Ws[e >> 6][e & 63] = Wt[(size_t)bh * (DH * DH) + e];
    __syncthreads();

    const int nn = tid >> 6;
    const int i = tid & 63;
    const size_t base = ((size_t)b * NN) * DD + h * DH;
    const int n0 = blockIdx.y * 64;

    for (int n = n0; n < n0 + 64; n += 4) {
        Vs[nn][i] = __half2float(vf[base + (size_t)(n + nn) * DD + i]);
        __syncthreads();
        float acc = 0.0f;
#pragma unroll
        for (int j = 0; j < DH; j++) acc += Ws[i][j] * Vs[nn][j];
        ohf[base + (size_t)(n + nn) * DD + i] = __float2half(acc);
        __syncthreads();
    }
}

// ===================== reduction finalize + norm =====================
__global__ void __launch_bounds__(256) red2_kernel(int nb)
{
    double a = 0.0, b = 0.0;
    for (int i = threadIdx.x; i < nb; i += 256) { a += g_part[i][0]; b += g_part[i][1]; }
    __shared__ double sa[256], sb[256];
    sa[threadIdx.x] = a;
    sb[threadIdx.x] = b;
    __syncthreads();
    for (int o = 128; o > 0; o >>= 1) {
        if (threadIdx.x < o) { sa[threadIdx.x] += sa[threadIdx.x + o]; sb[threadIdx.x] += sb[threadIdx.x + o]; }
        __syncthreads();
    }
    if (threadIdx.x == 0) { g_red[0] = sa[0]; g_red[1] = sb[0]; }
}

template <int OUTK> // 0 = fp32 only, 2 = also fp16
__global__ void __launch_bounds__(256) norm_kernel(
    const float* __restrict__ x, const float* __restrict__ alpha,
    const float* __restrict__ beta, const float* __restrict__ eps,
    float* __restrict__ y, __half* __restrict__ yh, size_t n)
{
    const double Md = (double)n;
    const double mean = g_red[0] / Md;
    const double var = (g_red[1] - Md * mean * mean) / (Md - 1.0);
    const float sd = (float)sqrt(var);

    const size_t n4 = n >> 2;
    const size_t stride = (size_t)gridDim.x * blockDim.x;
    for (size_t i4 = (size_t)blockIdx.x * blockDim.x + threadIdx.x; i4 < n4; i4 += stride) {
        float4 v = ((const float4*)x)[i4];
        const int d = (int)((i4 * 4) & (DD - 1));
        v.x = v.x / (sd + eps[d + 0]) * alpha[d + 0] + beta[d + 0];
        v.y = v.y / (sd + eps[d + 1]) * alpha[d + 1] + beta[d + 1];
        v.z = v.z / (sd + eps[d + 2]) * alpha[d + 2] + beta[d + 2];
        v.w = v.w / (sd + eps[d + 3]) * alpha[d + 3] + beta[d + 3];
        ((float4*)y)[i4] = v;
        if (OUTK == 2) {
            ((__half2*)yh)[i4 * 2 + 0] = __floats2half2_rn(v.x, v.y);
            ((__half2*)yh)[i4 * 2 + 1] = __floats2half2_rn(v.z, v.w);
        }
    }
}

// ===================== launch =====================
extern "C" void kernel_launch(void* const* d_in, const int* in_sizes, int n_in,
                              void* d_out, int out_size)
{
    const float* x    = (const float*)d_in[0];
    const float* wq_w = (const float*)d_in[1];
    const float* wq_b = (const float*)d_in[2];
    const float* wk_w = (const float*)d_in[3];
    const float* wk_b = (const float*)d_in[4];
    const float* wv_w = (const float*)d_in[5];
    const float* wv_b = (const float*)d_in[6];
    const float* wo_w = (const float*)d_in[7];
    const float* wo_b = (const float*)d_in[8];
    const float* w1   = (const float*)d_in[9];
    const float* b1   = (const float*)d_in[10];
    const float* w2   = (const float*)d_in[11];
    const float* b2   = (const float*)d_in[12];
    const float* an_a = (const float*)d_in[13];
    const float* an_b = (const float*)d_in[14];
    const float* an_e = (const float*)d_in[15];
    const float* mn_a = (const float*)d_in[16];
    const float* mn_b = (const float*)d_in[17];
    const float* mn_e = (const float*)d_in[18];
    float* out = (float*)d_out;

    float *attn, *out1, *Gpart, *Wt, *bqkv;
    cudaGetSymbolAddress((void**)&attn, g_attn);
    cudaGetSymbolAddress((void**)&out1, g_out1);
    cudaGetSymbolAddress((void**)&Gpart, g_Gpart);
    cudaGetSymbolAddress((void**)&Wt, g_Wt);
    cudaGetSymbolAddress((void**)&bqkv, g_bqkv);

    __half *xf, *qf, *kf, *vf, *apf, *wqkvf, *wof, *w1f, *w2f, *atf, *hf;
    cudaGetSymbolAddress((void**)&xf, g_xf);
    cudaGetSymbolAddress((void**)&qf, g_qf);
    cudaGetSymbolAddress((void**)&kf, g_kf);
    cudaGetSymbolAddress((void**)&vf, g_vf);
    cudaGetSymbolAddress((void**)&apf, g_apf);
    cudaGetSymbolAddress((void**)&wqkvf, g_wqkvf);
    cudaGetSymbolAddress((void**)&wof, g_wof);
    cudaGetSymbolAddress((void**)&w1f, g_w1f);
    cudaGetSymbolAddress((void**)&w2f, g_w2f);
    cudaGetSymbolAddress((void**)&atf, g_atf);
    cudaGetSymbolAddress((void**)&hf, g_hf);

    cudaFuncSetAttribute(gemm_f16<false, false, true,  false, true >, cudaFuncAttributeMaxDynamicSharedMemorySize, F16_SMEM);
    cudaFuncSetAttribute(gemm_f16<true,  false, false, true,  false>, cudaFuncAttributeMaxDynamicSharedMemorySize, F16_SMEM);
    cudaFuncSetAttribute(gemm_f16<false, true,  true,  false, false>, cudaFuncAttributeMaxDynamicSharedMemorySize, F16_SMEM);

    // ---- one merged conversion launch (x + all weights; qkv weights into one buffer) ----
    cvt_all_kernel<<<2048, 256>>>(x, wq_w, wk_w, wv_w, wo_w, w1, w2,
                                  xf, wqkvf + 0 * DD * DD, wqkvf + 1 * DD * DD,
                                  wqkvf + 2 * DD * DD, wof, w1f, w2f);
    cudaMemcpyAsync(bqkv + 0 * DD, wq_b, DD * sizeof(float), cudaMemcpyDeviceToDevice);
    cudaMemcpyAsync(bqkv + 1 * DD, wk_b, DD * sizeof(float), cudaMemcpyDeviceToDevice);
    cudaMemcpyAsync(bqkv + 2 * DD, wv_b, DD * sizeof(float), cudaMemcpyDeviceToDevice);

    const dim3 gQKV(QKVN / GW_BN, MM / GW_BM); // (24, 128) -> 3072 CTAs
    const dim3 gProj(DD / GW_BN, MM / GW_BM);  // (8, 128)
    const dim3 gMlp1(FF / GW_BN, MM / GW_BM);  // (32, 128)

    // ---- merged Q|K|V projection -> three contiguous fp16 buffers ----
    gemm_f16<false, false, true, false, true><<<gQKV, 256, F16_SMEM>>>(
        xf, wqkvf, bqkv, nullptr, nullptr, qf, kf, vf, MM, QKVN, DD);

    // ---- FFT attention (collapsed form) ----
    gram_kernel<<<dim3(BB * HH, 8), 256>>>(qf, kf, Gpart);
    weights_kernel<<<BB * HH, 256>>>(Gpart, Wt);
    applyw_kernel<<<dim3(BB * HH, NN / 64), 256>>>(vf, Wt, apf);

    // ---- output projection + residual (fp32 out), fused sum/sumsq ----
    gemm_f16<true, false, false, true, false><<<gProj, 256, F16_SMEM>>>(
        apf, wof, wo_b, x, attn, nullptr, nullptr, nullptr, MM, DD, DD);

    // ---- rmsnorm 1 (global std from fused partials), fp32 + fp16 outputs ----
    red2_kernel<<<1, 256>>>(1024);
    norm_kernel<2><<<2048, 256>>>(attn, an_a, an_b, an_e, attn, atf, TOT);

    // ---- MLP (fp16) ----
    gemm_f16<false, true, true, false, false><<<gMlp1, 256, F16_SMEM>>>(
        atf, w1f, b1, nullptr, nullptr, hf, nullptr, nullptr, MM, FF, DD);
    gemm_f16<true, false, false, true, false><<<gProj, 256, F16_SMEM>>>(
        hf, w2f, b2, attn, out1, nullptr, nullptr, nullptr, MM, DD, FF);

    // ---- rmsnorm 2 -> final fp32 output ----
    red2_kernel<<<1, 256>>>(1024);
    norm_kernel<0><<<2048, 256>>>(out1, mn_a, mn_b, mn_e, out, nullptr, TOT);
}

// round 16
// speedup vs baseline: 1.0342x; 1.0022x over previous
#include <cuda_runtime.h>
#include <cuda_fp16.h>
#include <cstdint>
#include <math.h>

// Problem dims (fixed by the dataset)
#define BB 4
#define NN 4096
#define DD 1024
#define HH 16
#define DH 64
#define FF 4096
#define MM (BB * NN)          // 16384
#define TOT ((size_t)MM * DD) // 16,777,216
#define QKVN (3 * DD)

// ===================== helpers =====================
__device__ __forceinline__ uint32_t smem_u32(const void* p) {
    uint32_t a;
    asm("{ .reg .u64 t; cvta.to.shared.u64 t, %1; cvt.u32.u64 %0, t; }" : "=r"(a) : "l"(p));
    return a;
}
__device__ __forceinline__ void cp_async16(uint32_t dst, const void* src) {
    asm volatile("cp.async.cg.shared.global [%0], [%1], 16;"
                 :: "r"(dst), "l"(__cvta_generic_to_global(src)));
}
__device__ __forceinline__ void cp_commit() { asm volatile("cp.async.commit_group;" ::: "memory"); }
__device__ __forceinline__ void cp_wait0()  { asm volatile("cp.async.wait_group 0;" ::: "memory"); }
__device__ __forceinline__ void cp_wait1()  { asm volatile("cp.async.wait_group 1;" ::: "memory"); }

#define MMAF16(d, a, b0, b1) \
    asm volatile("mma.sync.aligned.m16n8k16.row.col.f32.f16.f16.f32 " \
        "{%0,%1,%2,%3}, {%4,%5,%6,%7}, {%8,%9}, {%0,%1,%2,%3};" \
        : "+f"((d)[0]), "+f"((d)[1]), "+f"((d)[2]), "+f"((d)[3]) \
        : "r"((a)[0]), "r"((a)[1]), "r"((a)[2]), "r"((a)[3]), "r"(b0), "r"(b1))

#define LDMX4(r, addr) \
    asm volatile("ldmatrix.sync.aligned.m8n8.x4.shared.b16 {%0,%1,%2,%3}, [%4];" \
        : "=r"((r)[0]), "=r"((r)[1]), "=r"((r)[2]), "=r"((r)[3]) : "r"(addr))

// ===================== scratch (static device globals) =====================
__device__ float g_attn[MM * DD];
__device__ float g_out1[MM * DD];
__device__ float g_Gpart[BB * HH * 8 * DH * DH];
__device__ float g_Wt[BB * HH * DH * DH];
__device__ float g_bqkv[QKVN];
__device__ double g_part[4096][2];

// fp16 operands
__device__ __half g_xf[MM * DD];
__device__ __half g_qf[MM * DD];
__device__ __half g_kf[MM * DD];
__device__ __half g_vf[MM * DD];
__device__ __half g_apf[MM * DD];          // attnpre (weighted V)
__device__ __half g_wqkvf[3 * DD * DD];    // wq | wk | wv concatenated along N
__device__ __half g_wof[DD * DD];
__device__ __half g_w1f[FF * DD];
__device__ __half g_w2f[DD * FF];
__device__ __half g_atf[MM * DD];
__device__ __half g_hf[(size_t)MM * FF];

// ===================== merged fp32 -> fp16 convert (x + all weights) ==========
__global__ void __launch_bounds__(256) cvt_all_kernel(
    const float* __restrict__ x,  const float* __restrict__ wq,
    const float* __restrict__ wk, const float* __restrict__ wv,
    const float* __restrict__ wo, const float* __restrict__ w1,
    const float* __restrict__ w2,
    __half* __restrict__ xf,  __half* __restrict__ wqf,
    __half* __restrict__ wkf, __half* __restrict__ wvf,
    __half* __restrict__ wof, __half* __restrict__ w1f,
    __half* __restrict__ w2f)
{
    const size_t SX = TOT / 4;
    const size_t SW = (size_t)DD * DD / 4;
    const size_t SF = (size_t)FF * DD / 4;
    const size_t e0 = SX;
    const size_t e1 = e0 + SW;
    const size_t e2 = e1 + SW;
    const size_t e3 = e2 + SW;
    const size_t e4 = e3 + SW;
    const size_t e5 = e4 + SF;
    const size_t e6 = e5 + SF;
    const size_t stride = (size_t)gridDim.x * blockDim.x;
    for (size_t i = (size_t)blockIdx.x * blockDim.x + threadIdx.x; i < e6; i += stride) {
        const float* s; __half* d; size_t off;
        if (i < e0)      { s = x;  d = xf;  off = i; }
        else if (i < e1) { s = wq; d = wqf; off = i - e0; }
        else if (i < e2) { s = wk; d = wkf; off = i - e1; }
        else if (i < e3) { s = wv; d = wvf; off = i - e2; }
        else if (i < e4) { s = wo; d = wof; off = i - e3; }
        else if (i < e5) { s = w1; d = w1f; off = i - e4; }
        else             { s = w2; d = w2f; off = i - e5; }
        float4 v = ((const float4*)s)[off];
        ((__half2*)d)[off * 2 + 0] = __floats2half2_rn(v.x, v.y);
        ((__half2*)d)[off * 2 + 1] = __floats2half2_rn(v.z, v.w);
    }
}

// ===================== fp16 single-product HMMA GEMM =====================
#define GW_BM 128
#define GW_BN 128
#define GW_BK 32
#define ROWB 80
#define BUFB (128 * ROWB)
#define F16_STAGEB (2 * BUFB)          // 20480 per stage (A + B)
#define NSTAGE 3
#define F16_SMEM (NSTAGE * F16_STAGEB) // 61440

// OUT3: route fp16 output to one of {Ch, Ch2, Ch3} by bn>>10, each with row stride DD
template <bool HAS_RES, bool GELU, bool OUTF16, bool DO_RED, bool OUT3>
__global__ void __launch_bounds__(256, 2) gemm_f16(
    const __half* __restrict__ A, const __half* __restrict__ B,
    const float* __restrict__ bias, const float* __restrict__ res,
    float* __restrict__ Cf, __half* __restrict__ Ch,
    __half* __restrict__ Ch2, __half* __restrict__ Ch3,
    int M, int N, int K)
{
    extern __shared__ char sm[];
    const int tid = threadIdx.x;
    const int wid = tid >> 5;
    const int lane = tid & 31;
    const int wm = wid & 3;
    const int wn = wid >> 2;
    const int bm = blockIdx.y * GW_BM;
    const int bn = blockIdx.x * GW_BN;
    const int KT = K / GW_BK;
    const uint32_t smb = smem_u32(sm);

    auto load_stage = [&](int kt) {
        const uint32_t sb = smb + (uint32_t)(kt % NSTAGE) * F16_STAGEB;
        const int k0 = kt * GW_BK;
#pragma unroll
        for (int i = 0; i < 4; i++) {
            const int c = tid + i * 256;
            const int buf = c >> 9;
            const int cc = c & 511;
            const int row = cc >> 2;
            const int qq = cc & 3;
            const __half* gb = buf ? B : A;
            const int grow = (buf ? bn : bm) + row;
            const void* src = gb + (size_t)grow * K + k0 + qq * 8;
            cp_async16(sb + buf * BUFB + row * ROWB + qq * 16, src);
        }
    };

    float acc[2][8][4];
#pragma unroll
    for (int mt = 0; mt < 2; mt++)
#pragma unroll
        for (int nt = 0; nt < 8; nt++)
#pragma unroll
            for (int r = 0; r < 4; r++) acc[mt][nt][r] = 0.0f;

    load_stage(0);
    cp_commit();
    if (KT > 1) { load_stage(1); cp_commit(); }

    const int lr = lane & 7;
    const int a_row = wm * 32 + lr + ((lane & 8) ? 8 : 0);
    const int a_kb  = (lane & 16) ? 16 : 0;
    const int b_row = wn * 64 + lr + ((lane & 16) ? 8 : 0);
    const int b_kb  = (lane & 8) ? 16 : 0;

    for (int kt = 0; kt < KT; kt++) {
        if (kt + 1 < KT) cp_wait1(); else cp_wait0();
        __syncthreads();   // single barrier per kt

        if (kt + 2 < KT) {
            load_stage(kt + 2);
            cp_commit();
        }

        const uint32_t sb = smb + (uint32_t)(kt % NSTAGE) * F16_STAGEB;
        const uint32_t As = sb;
        const uint32_t Bs = sb + BUFB;

#pragma unroll
        for (int k16 = 0; k16 < 2; k16++) {
            const int kc = k16 * 32;
            uint32_t af[2][4];
            uint32_t bf[4][4];
#pragma unroll
            for (int mt = 0; mt < 2; mt++)
                LDMX4(af[mt], As + (uint32_t)((a_row + mt * 16) * ROWB + kc + a_kb));
#pragma unroll
            for (int p = 0; p < 4; p++)
                LDMX4(bf[p], Bs + (uint32_t)((b_row + p * 16) * ROWB + kc + b_kb));
#pragma unroll
            for (int p = 0; p < 4; p++)
#pragma unroll
                for (int sub = 0; sub < 2; sub++) {
                    const int nt = p * 2 + sub;
#pragma unroll
                    for (int mt = 0; mt < 2; mt++)
                        MMAF16(acc[mt][nt], af[mt], bf[p][sub * 2], bf[p][sub * 2 + 1]);
                }
        }
    }

    // output routing for OUT3 (uniform per CTA: bn is a multiple of 128)
    __half* Co = Ch;
    int cofs = 0;
    if (OUT3) {
        const int seg = bn >> 10;
        Co = (seg == 0) ? Ch : (seg == 1) ? Ch2 : Ch3;
        cofs = seg << 10;
    }

    float rs = 0.0f, rs2 = 0.0f;

#pragma unroll
    for (int mt = 0; mt < 2; mt++) {
        const int r0 = bm + wm * 32 + mt * 16 + (lane >> 2);
#pragma unroll
        for (int nt = 0; nt < 8; nt++) {
            const int c = bn + wn * 64 + nt * 8 + ((lane & 3) << 1);
            const float b0 = bias[c], b1 = bias[c + 1];
#pragma unroll
            for (int half = 0; half < 2; half++) {
                const int row = r0 + half * 8;
                float v0 = acc[mt][nt][half * 2 + 0] + b0;
                float v1 = acc[mt][nt][half * 2 + 1] + b1;
                if (HAS_RES) {
                    const float2 rr = *(const float2*)(res + (size_t)row * N + c);
                    v0 += rr.x; v1 += rr.y;
                }
                if (GELU) {
                    v0 = 0.5f * v0 * (1.0f + erff(v0 * 0.70710678118654752f));
                    v1 = 0.5f * v1 * (1.0f + erff(v1 * 0.70710678118654752f));
                }
                if (DO_RED) {
                    rs += v0 + v1;
                    rs2 += v0 * v0 + v1 * v1;
                }
                if (OUTF16) {
                    if (OUT3)
                        *(__half2*)(Co + (size_t)row * DD + (c - cofs)) = __floats2half2_rn(v0, v1);
                    else
                        *(__half2*)(Ch + (size_t)row * N + c) = __floats2half2_rn(v0, v1);
                } else {
                    float2 o; o.x = v0; o.y = v1;
                    *(float2*)(Cf + (size_t)row * N + c) = o;
                }
            }
        }
    }

    if (DO_RED) {
#pragma unroll
        for (int o = 16; o > 0; o >>= 1) {
            rs += __shfl_down_sync(0xFFFFFFFFu, rs, o);
            rs2 += __shfl_down_sync(0xFFFFFFFFu, rs2, o);
        }
        __shared__ float shr[2][8];
        if (lane == 0) { shr[0][wid] = rs; shr[1][wid] = rs2; }
        __syncthreads();
        if (tid == 0) {
            double a = 0.0, b = 0.0;
#pragma unroll
            for (int i = 0; i < 8; i++) { a += (double)shr[0][i]; b += (double)shr[1][i]; }
            const int cid = blockIdx.y * gridDim.x + blockIdx.x;
            g_part[cid][0] = a;
            g_part[cid][1] = b;
        }
    }
}

// ===================== attention small ops =====================
__global__ void __launch_bounds__(256) gram_kernel(
    const __half* __restrict__ qf, const __half* __restrict__ kf,
    float* __restrict__ Gpart)
{
    const int bh = blockIdx.x;
    const int ns = blockIdx.y;
    const int b = bh >> 4, h = bh & 15;
    const int tid = threadIdx.x;
    __shared__ float Qs[32][68];
    __shared__ float Ks[32][68];

    float acc[4][4];
#pragma unroll
    for (int i = 0; i < 4; i++)
#pragma unroll
        for (int j = 0; j < 4; j++) acc[i][j] = 0.0f;

    const int ty = tid >> 4, tx = tid & 15;
    const size_t base = ((size_t)b * NN) * DD + h * DH;
    const int n0s = ns * 512;

    const int lrow = tid >> 3;
    const int lch  = tid & 7;

    for (int n0 = n0s; n0 < n0s + 512; n0 += 32) {
        const size_t roff = base + (size_t)(n0 + lrow) * DD + lch * 8;
        const uint4 qv = *(const uint4*)(qf + roff);
        const uint4 kv = *(const uint4*)(kf + roff);
        {
            float2 f0 = __half22float2(*(const __half2*)&qv.x);
            float2 f1 = __half22float2(*(const __half2*)&qv.y);
            float2 f2 = __half22float2(*(const __half2*)&qv.z);
            float2 f3 = __half22float2(*(const __half2*)&qv.w);
            float4 a; a.x = f0.x; a.y = f0.y; a.z = f1.x; a.w = f1.y;
            float4 c; c.x = f2.x; c.y = f2.y; c.z = f3.x; c.w = f3.y;
            *(float4*)&Qs[lrow][lch * 8] = a;
            *(float4*)&Qs[lrow][lch * 8 + 4] = c;
        }
        {
            float2 f0 = __half22float2(*(const __half2*)&kv.x);
            float2 f1 = __half22float2(*(const __half2*)&kv.y);
            float2 f2 = __half22float2(*(const __half2*)&kv.z);
            float2 f3 = __half22float2(*(const __half2*)&kv.w);
            float4 a; a.x = f0.x; a.y = f0.y; a.z = f1.x; a.w = f1.y;
            float4 c; c.x = f2.x; c.y = f2.y; c.z = f3.x; c.w = f3.y;
            *(float4*)&Ks[lrow][lch * 8] = a;
            *(float4*)&Ks[lrow][lch * 8 + 4] = c;
        }
        __syncthreads();
#pragma unroll
        for (int kk = 0; kk < 32; kk++) {
            float qr[4], kr[4];
#pragma unroll
            for (int i = 0; i < 4; i++) qr[i] = Qs[kk][ty * 4 + i];
#pragma unroll
            for (int j = 0; j < 4; j++) kr[j] = Ks[kk][tx * 4 + j];
#pragma unroll
            for (int i = 0; i < 4; i++)
#pragma unroll
                for (int j = 0; j < 4; j++) acc[i][j] += qr[i] * kr[j];
        }
        __syncthreads();
    }

    float* Gout = Gpart + ((size_t)bh * 8 + ns) * (DH * DH);
#pragma unroll
    for (int i = 0; i < 4; i++)
#pragma unroll
        for (int j = 0; j < 4; j++)
            Gout[(ty * 4 + i) * DH + tx * 4 + j] = acc[i][j];
}

// row-split DFT-magnitude: grid (BB*HH, 4); chunk = 16 rows; bitwise identical per output
__global__ void __launch_bounds__(256) weights_kernel(
    const float* __restrict__ Gpart, float* __restrict__ Wt)
{
    const int bh = blockIdx.x;
    const int rc = blockIdx.y;          // row chunk 0..3 (16 rows each)
    const int tid = threadIdx.x;
    __shared__ float Gs[16][DH];
    __shared__ float ct[DH], st[DH];

    const int r0 = rc * 16;
    for (int e = tid; e < 16 * DH; e += 256) {
        const int rr = e >> 6, cc = e & 63;
        float sacc = 0.0f;
#pragma unroll
        for (int p = 0; p < 8; p++)
            sacc += Gpart[((size_t)bh * 8 + p) * (DH * DH) + (r0 + rr) * DH + cc];
        Gs[rr][cc] = sacc;
    }
    if (tid < DH) {
        float a = 6.283185307179586f * (float)tid / 64.0f;
        ct[tid] = cosf(a);
        st[tid] = sinf(a);
    }
    __syncthreads();

    const int rr = tid >> 4;            // 0..15 local row
    const int j0 = (tid & 15) * 4;      // 16 threads per row, 4 j's each
    for (int jj = 0; jj < 4; jj++) {
        const int j = j0 + jj;
        float re = 0.0f, im = 0.0f;
#pragma unroll
        for (int kk = 0; kk < DH; kk++) {
            const int t = (kk * j) & 63;
            const float g = Gs[rr][kk];
            re += g * ct[t];
            im += g * st[t];
        }
        Wt[(size_t)bh * (DH * DH) + (r0 + rr) * DH + j] = sqrtf(re * re + im * im);
    }
}

__global__ void __launch_bounds__(256) applyw_kernel(
    const __half* __restrict__ vf, const float* __restrict__ Wt,
    __half* __restrict__ ohf)
{
    const int bh = blockIdx.x;
    const int b = bh >> 4, h = bh & 15;
    const int tid = threadIdx.x;
    __shared__ float Ws[DH][DH + 1];
    __shared__ float Vs[4][DH];

    for (int e = tid; e < DH * DH; e += 256)
        Ws[e >> 6][e & 63] = Wt[(size_t)bh * (DH * DH) + e];
    __syncthreads();

    const int nn = tid >> 6;
    const int i = tid & 63;
    const size_t base = ((size_t)b * NN) * DD + h * DH;
    const int n0 = blockIdx.y * 64;

    for (int n = n0; n < n0 + 64; n += 4) {
        Vs[nn][i] = __half2float(vf[base + (size_t)(n + nn) * DD + i]);
        __syncthreads();
        float acc = 0.0f;
#pragma unroll
        for (int j = 0; j < DH; j++) acc += Ws[i][j] * Vs[nn][j];
        ohf[base + (size_t)(n + nn) * DD + i] = __float2half(acc);
        __syncthreads();
    }
}

// ===================== norm with inline partial reduction (red2 folded in) ====
template <int OUTK> // 0 = fp32 only, 2 = also fp16
__global__ void __launch_bounds__(256) norm_kernel(
    const float* __restrict__ x, const float* __restrict__ alpha,
    const float* __restrict__ beta, const float* __restrict__ eps,
    float* __restrict__ y, __half* __restrict__ yh, size_t n, int nb)
{
    // per-CTA reduction of the GEMM partials (identical order to old red2 -> same bits)
    __shared__ double sa[256], sb[256];
    {
        double a = 0.0, b = 0.0;
        for (int i = threadIdx.x; i < nb; i += 256) { a += g_part[i][0]; b += g_part[i][1]; }
        sa[threadIdx.x] = a;
        sb[threadIdx.x] = b;
        __syncthreads();
        for (int o = 128; o > 0; o >>= 1) {
            if (threadIdx.x < o) { sa[threadIdx.x] += sa[threadIdx.x + o]; sb[threadIdx.x] += sb[threadIdx.x + o]; }
            __syncthreads();
        }
    }
    const double Md = (double)n;
    const double mean = sa[0] / Md;
    const double var = (sb[0] - Md * mean * mean) / (Md - 1.0);
    const float sd = (float)sqrt(var);

    const size_t n4 = n >> 2;
    const size_t stride = (size_t)gridDim.x * blockDim.x;
    for (size_t i4 = (size_t)blockIdx.x * blockDim.x + threadIdx.x; i4 < n4; i4 += stride) {
        float4 v = ((const float4*)x)[i4];
        const int d = (int)((i4 * 4) & (DD - 1));
        v.x = v.x / (sd + eps[d + 0]) * alpha[d + 0] + beta[d + 0];
        v.y = v.y / (sd + eps[d + 1]) * alpha[d + 1] + beta[d + 1];
        v.z = v.z / (sd + eps[d + 2]) * alpha[d + 2] + beta[d + 2];
        v.w = v.w / (sd + eps[d + 3]) * alpha[d + 3] + beta[d + 3];
        ((float4*)y)[i4] = v;
        if (OUTK == 2) {
            ((__half2*)yh)[i4 * 2 + 0] = __floats2half2_rn(v.x, v.y);
            ((__half2*)yh)[i4 * 2 + 1] = __floats2half2_rn(v.z, v.w);
        }
    }
}

// ===================== launch =====================
extern "C" void kernel_launch(void* const* d_in, const int* in_sizes, int n_in,
                              void* d_out, int out_size)
{
    const float* x    = (const float*)d_in[0];
    const float* wq_w = (const float*)d_in[1];
    const float* wq_b = (const float*)d_in[2];
    const float* wk_w = (const float*)d_in[3];
    const float* wk_b = (const float*)d_in[4];
    const float* wv_w = (const float*)d_in[5];
    const float* wv_b = (const float*)d_in[6];
    const float* wo_w = (const float*)d_in[7];
    const float* wo_b = (const float*)d_in[8];
    const float* w1   = (const float*)d_in[9];
    const float* b1   = (const float*)d_in[10];
    const float* w2   = (const float*)d_in[11];
    const float* b2   = (const float*)d_in[12];
    const float* an_a = (const float*)d_in[13];
    const float* an_b = (const float*)d_in[14];
    const float* an_e = (const float*)d_in[15];
    const float* mn_a = (const float*)d_in[16];
    const float* mn_b = (const float*)d_in[17];
    const float* mn_e = (const float*)d_in[18];
    float* out = (float*)d_out;

    float *attn, *out1, *Gpart, *Wt, *bqkv;
    cudaGetSymbolAddress((void**)&attn, g_attn);
    cudaGetSymbolAddress((void**)&out1, g_out1);
    cudaGetSymbolAddress((void**)&Gpart, g_Gpart);
    cudaGetSymbolAddress((void**)&Wt, g_Wt);
    cudaGetSymbolAddress((void**)&bqkv, g_bqkv);

    __half *xf, *qf, *kf, *vf, *apf, *wqkvf, *wof, *w1f, *w2f, *atf, *hf;
    cudaGetSymbolAddress((void**)&xf, g_xf);
    cudaGetSymbolAddress((void**)&qf, g_qf);
    cudaGetSymbolAddress((void**)&kf, g_kf);
    cudaGetSymbolAddress((void**)&vf, g_vf);
    cudaGetSymbolAddress((void**)&apf, g_apf);
    cudaGetSymbolAddress((void**)&wqkvf, g_wqkvf);
    cudaGetSymbolAddress((void**)&wof, g_wof);
    cudaGetSymbolAddress((void**)&w1f, g_w1f);
    cudaGetSymbolAddress((void**)&w2f, g_w2f);
    cudaGetSymbolAddress((void**)&atf, g_atf);
    cudaGetSymbolAddress((void**)&hf, g_hf);

    cudaFuncSetAttribute(gemm_f16<false, false, true,  false, true >, cudaFuncAttributeMaxDynamicSharedMemorySize, F16_SMEM);
    cudaFuncSetAttribute(gemm_f16<true,  false, false, true,  false>, cudaFuncAttributeMaxDynamicSharedMemorySize, F16_SMEM);
    cudaFuncSetAttribute(gemm_f16<false, true,  true,  false, false>, cudaFuncAttributeMaxDynamicSharedMemorySize, F16_SMEM);

    // ---- one merged conversion launch (x + all weights; qkv weights into one buffer) ----
    cvt_all_kernel<<<2048, 256>>>(x, wq_w, wk_w, wv_w, wo_w, w1, w2,
                                  xf, wqkvf + 0 * DD * DD, wqkvf + 1 * DD * DD,
                                  wqkvf + 2 * DD * DD, wof, w1f, w2f);
    cudaMemcpyAsync(bqkv + 0 * DD, wq_b, DD * sizeof(float), cudaMemcpyDeviceToDevice);
    cudaMemcpyAsync(bqkv + 1 * DD, wk_b, DD * sizeof(float), cudaMemcpyDeviceToDevice);
    cudaMemcpyAsync(bqkv + 2 * DD, wv_b, DD * sizeof(float), cudaMemcpyDeviceToDevice);

    const dim3 gQKV(QKVN / GW_BN, MM / GW_BM); // (24, 128) -> 3072 CTAs
    const dim3 gProj(DD / GW_BN, MM / GW_BM);  // (8, 128)
    const dim3 gMlp1(FF / GW_BN, MM / GW_BM);  // (32, 128)

    // ---- merged Q|K|V projection -> three contiguous fp16 buffers ----
    gemm_f16<false, false, true, false, true><<<gQKV, 256, F16_SMEM>>>(
        xf, wqkvf, bqkv, nullptr, nullptr, qf, kf, vf, MM, QKVN, DD);

    // ---- FFT attention (collapsed form) ----
    gram_kernel<<<dim3(BB * HH, 8), 256>>>(qf, kf, Gpart);
    weights_kernel<<<dim3(BB * HH, 4), 256>>>(Gpart, Wt);
    applyw_kernel<<<dim3(BB * HH, NN / 64), 256>>>(vf, Wt, apf);

    // ---- output projection + residual (fp32 out), fused sum/sumsq ----
    gemm_f16<true, false, false, true, false><<<gProj, 256, F16_SMEM>>>(
        apf, wof, wo_b, x, attn, nullptr, nullptr, nullptr, MM, DD, DD);

    // ---- rmsnorm 1 (partials reduced in-kernel), fp32 + fp16 outputs ----
    norm_kernel<2><<<2048, 256>>>(attn, an_a, an_b, an_e, attn, atf, TOT, 1024);

    // ---- MLP (fp16) ----
    gemm_f16<false, true, true, false, false><<<gMlp1, 256, F16_SMEM>>>(
        atf, w1f, b1, nullptr, nullptr, hf, nullptr, nullptr, MM, FF, DD);
    gemm_f16<true, false, false, true, false><<<gProj, 256, F16_SMEM>>>(
        hf, w2f, b2, attn, out1, nullptr, nullptr, nullptr, MM, DD, FF);

    // ---- rmsnorm 2 -> final fp32 output ----
    norm_kernel<0><<<2048, 256>>>(out1, mn_a, mn_b, mn_e, out, nullptr, TOT, 1024);
}